// round 1
// baseline (speedup 1.0000x reference)
#include <cuda_runtime.h>

// Problem constants
#define BNUM 4
#define SEQ  1024
#define EMBD 1024
#define NH   16
#define HD   64
#define BH   (BNUM * NH)
#define ATT_SCALE (1.0f / 32.0f)   // 1/sqrt(1024), applied to (logits+mask)

#define NEG_INF __int_as_float(0xff800000)

// Scratch (allocation-free contract: __device__ globals)
// layout [b*NH+h][s][d]
__device__ float g_q[BH * SEQ * HD];
__device__ float g_k[BH * SEQ * HD];
__device__ float g_v[BH * SEQ * HD];
// concat ctx layout [b][s][h*64+d] == [4096][1024]
__device__ float g_ctx[BNUM * SEQ * EMBD];

// ---------------------------------------------------------------------------
// Projection GEMM: for z in {K,V,Q}:  C[m, n] = sum_k X[m,k] * W[n>>6, k, n&63]
// M = 4096 (b*s), N = 1024 (h*64+d), K = 1024.
// 128x128 tile, BK=8, 256 threads, 8x8 per-thread microtile.
// Output written directly into [bh][s][d] layout.
// ---------------------------------------------------------------------------
__global__ __launch_bounds__(256) void proj_kernel(
    const float* __restrict__ Xk, const float* __restrict__ Xv,
    const float* __restrict__ Xq,
    const float* __restrict__ Wk, const float* __restrict__ Wv,
    const float* __restrict__ Wq)
{
    const float* X;
    const float* W;
    float* Out;
    if (blockIdx.z == 0)      { X = Xk; W = Wk; Out = g_k; }
    else if (blockIdx.z == 1) { X = Xv; W = Wv; Out = g_v; }
    else                      { X = Xq; W = Wq; Out = g_q; }

    __shared__ float As[8][128];
    __shared__ float Bs[8][128];

    const int tid  = threadIdx.x;
    const int tx   = tid & 15;
    const int ty   = tid >> 4;
    const int row0 = blockIdx.x * 128;
    const int col0 = blockIdx.y * 128;

    // A loader: thread -> (row, 4 consecutive k)
    const int ar = tid >> 1;
    const int ac = (tid & 1) * 4;
    // B loader: thread -> (k-row bc, 4 consecutive n)
    const int bc = tid >> 5;
    const int bn = (tid & 31) * 4;
    const int ng = col0 + bn;            // 4 consecutive n, same head block

    float acc[8][8] = {};

    for (int k0 = 0; k0 < EMBD; k0 += 8) {
        float4 av = *(const float4*)(X + (size_t)(row0 + ar) * EMBD + k0 + ac);
        As[ac + 0][ar] = av.x;
        As[ac + 1][ar] = av.y;
        As[ac + 2][ar] = av.z;
        As[ac + 3][ar] = av.w;

        float4 bv = *(const float4*)(W +
            (size_t)((ng >> 6) * EMBD + (k0 + bc)) * HD + (ng & 63));
        *(float4*)&Bs[bc][bn] = bv;
        __syncthreads();

        #pragma unroll
        for (int c = 0; c < 8; c++) {
            float4 a0 = *(float4*)&As[c][ty * 8];
            float4 a1 = *(float4*)&As[c][ty * 8 + 4];
            float4 b0 = *(float4*)&Bs[c][tx * 8];
            float4 b1 = *(float4*)&Bs[c][tx * 8 + 4];
            float a[8] = {a0.x, a0.y, a0.z, a0.w, a1.x, a1.y, a1.z, a1.w};
            float b[8] = {b0.x, b0.y, b0.z, b0.w, b1.x, b1.y, b1.z, b1.w};
            #pragma unroll
            for (int i = 0; i < 8; i++)
                #pragma unroll
                for (int j = 0; j < 8; j++)
                    acc[i][j] = fmaf(a[i], b[j], acc[i][j]);
        }
        __syncthreads();
    }

    #pragma unroll
    for (int i = 0; i < 8; i++) {
        const int m = row0 + ty * 8 + i;
        const int b = m >> 10;
        const int s = m & 1023;
        #pragma unroll
        for (int j = 0; j < 8; j++) {
            const int n = col0 + tx * 8 + j;
            const int h = n >> 6;
            const int d = n & 63;
            Out[(size_t)((b * NH + h) * SEQ + s) * HD + d] = acc[i][j];
        }
    }
}

// ---------------------------------------------------------------------------
// Flash-style causal attention. One block per (bh, q-tile of 64).
// 256 threads = 16x16, each owns a 4x4 microtile of the 64x64 S / O tiles.
// Online softmax state (m, l) in shared; O accumulator in registers.
// Writes ctx directly in concat layout [b][s][h*64+d].
// ---------------------------------------------------------------------------
#define QP 65   // padded pitch to kill bank conflicts

__global__ __launch_bounds__(256) void attn_kernel()
{
    extern __shared__ float sm[];
    float* Qs   = sm;                 // 64 x 65
    float* Ks   = Qs + 64 * QP;       // 64 x 65
    float* Vs   = Ks + 64 * QP;       // 64 x 65
    float* Ss   = Vs + 64 * QP;       // 64 x 65 (S tile, then P tile)
    float* mrow = Ss + 64 * QP;       // 64
    float* lrow = mrow + 64;          // 64
    float* arow = lrow + 64;          // 64

    const int bh = blockIdx.x;
    const int qt = blockIdx.y;
    const int q0 = qt * 64;
    const int tid = threadIdx.x;
    const int tx = tid & 15;
    const int ty = tid >> 4;

    const float* Qg = g_q + (size_t)bh * SEQ * HD;
    const float* Kg = g_k + (size_t)bh * SEQ * HD;
    const float* Vg = g_v + (size_t)bh * SEQ * HD;

    for (int idx = tid; idx < 64 * 64; idx += 256) {
        const int r = idx >> 6;
        const int d = idx & 63;
        Qs[r * QP + d] = Qg[(size_t)(q0 + r) * HD + d];
    }
    if (tid < 64) { mrow[tid] = NEG_INF; lrow[tid] = 0.0f; }

    float o[4][4] = {};

    for (int kt = 0; kt <= qt; kt++) {
        const int k0 = kt * 64;
        for (int idx = tid; idx < 64 * 64; idx += 256) {
            const int r = idx >> 6;
            const int d = idx & 63;
            Ks[r * QP + d] = Kg[(size_t)(k0 + r) * HD + d];
            Vs[r * QP + d] = Vg[(size_t)(k0 + r) * HD + d];
        }
        __syncthreads();

        // S = Q K^T  (64x64, reduce over 64)
        float sacc[4][4] = {};
        #pragma unroll 8
        for (int d = 0; d < 64; d++) {
            float a[4], b[4];
            #pragma unroll
            for (int i = 0; i < 4; i++) a[i] = Qs[(ty * 4 + i) * QP + d];
            #pragma unroll
            for (int j = 0; j < 4; j++) b[j] = Ks[(tx * 4 + j) * QP + d];
            #pragma unroll
            for (int i = 0; i < 4; i++)
                #pragma unroll
                for (int j = 0; j < 4; j++)
                    sacc[i][j] = fmaf(a[i], b[j], sacc[i][j]);
        }

        const bool diag = (kt == qt);
        #pragma unroll
        for (int i = 0; i < 4; i++) {
            const int q = q0 + ty * 4 + i;
            #pragma unroll
            for (int j = 0; j < 4; j++) {
                const int k = k0 + tx * 4 + j;
                float v = sacc[i][j] * ATT_SCALE;
                if (diag && k > q) v = NEG_INF;
                Ss[(ty * 4 + i) * QP + (tx * 4 + j)] = v;
            }
        }
        __syncthreads();

        // Online softmax: one thread per row
        if (tid < 64) {
            const int r = tid;
            const float mold = mrow[r];
            float mx = mold;
            #pragma unroll 8
            for (int j = 0; j < 64; j++) mx = fmaxf(mx, Ss[r * QP + j]);
            const float al = __expf(mold - mx);   // first tile: exp(-inf)=0
            float sum = 0.0f;
            #pragma unroll 8
            for (int j = 0; j < 64; j++) {
                const float p = __expf(Ss[r * QP + j] - mx);
                Ss[r * QP + j] = p;
                sum += p;
            }
            mrow[r] = mx;
            lrow[r] = lrow[r] * al + sum;
            arow[r] = al;
        }
        __syncthreads();

        // O = O*alpha + P V
        float al[4];
        #pragma unroll
        for (int i = 0; i < 4; i++) {
            al[i] = arow[ty * 4 + i];
            #pragma unroll
            for (int jj = 0; jj < 4; jj++) o[i][jj] *= al[i];
        }
        #pragma unroll 8
        for (int j = 0; j < 64; j++) {
            float p[4], v[4];
            #pragma unroll
            for (int i = 0; i < 4; i++) p[i] = Ss[(ty * 4 + i) * QP + j];
            #pragma unroll
            for (int jj = 0; jj < 4; jj++) v[jj] = Vs[j * QP + (tx * 4 + jj)];
            #pragma unroll
            for (int i = 0; i < 4; i++)
                #pragma unroll
                for (int jj = 0; jj < 4; jj++)
                    o[i][jj] = fmaf(p[i], v[jj], o[i][jj]);
        }
        __syncthreads();   // protect Ks/Vs/Ss before next tile's load
    }

    const int b = bh >> 4;
    const int h = bh & 15;
    #pragma unroll
    for (int i = 0; i < 4; i++) {
        const int q = q0 + ty * 4 + i;
        const float linv = 1.0f / lrow[ty * 4 + i];
        #pragma unroll
        for (int jj = 0; jj < 4; jj++) {
            const int d = tx * 4 + jj;
            g_ctx[(size_t)(b * SEQ + q) * EMBD + h * 64 + d] = o[i][jj] * linv;
        }
    }
}

// ---------------------------------------------------------------------------
// Output projection: out = relu(ctx @ Wo + bo), M=4096, N=1024, K=1024.
// Same 128x128x8 SGEMM scheme; Wo is plain row-major [K, N].
// ---------------------------------------------------------------------------
__global__ __launch_bounds__(256) void out_kernel(
    const float* __restrict__ Wo, const float* __restrict__ bo,
    float* __restrict__ out)
{
    __shared__ float As[8][128];
    __shared__ float Bs[8][128];

    const int tid  = threadIdx.x;
    const int tx   = tid & 15;
    const int ty   = tid >> 4;
    const int row0 = blockIdx.x * 128;
    const int col0 = blockIdx.y * 128;

    const int ar = tid >> 1;
    const int ac = (tid & 1) * 4;
    const int bc = tid >> 5;
    const int bn = (tid & 31) * 4;

    float acc[8][8] = {};

    for (int k0 = 0; k0 < EMBD; k0 += 8) {
        float4 av = *(const float4*)(g_ctx + (size_t)(row0 + ar) * EMBD + k0 + ac);
        As[ac + 0][ar] = av.x;
        As[ac + 1][ar] = av.y;
        As[ac + 2][ar] = av.z;
        As[ac + 3][ar] = av.w;

        float4 bv = *(const float4*)(Wo + (size_t)(k0 + bc) * EMBD + col0 + bn);
        *(float4*)&Bs[bc][bn] = bv;
        __syncthreads();

        #pragma unroll
        for (int c = 0; c < 8; c++) {
            float4 a0 = *(float4*)&As[c][ty * 8];
            float4 a1 = *(float4*)&As[c][ty * 8 + 4];
            float4 b0 = *(float4*)&Bs[c][tx * 8];
            float4 b1 = *(float4*)&Bs[c][tx * 8 + 4];
            float a[8] = {a0.x, a0.y, a0.z, a0.w, a1.x, a1.y, a1.z, a1.w};
            float b[8] = {b0.x, b0.y, b0.z, b0.w, b1.x, b1.y, b1.z, b1.w};
            #pragma unroll
            for (int i = 0; i < 8; i++)
                #pragma unroll
                for (int j = 0; j < 8; j++)
                    acc[i][j] = fmaf(a[i], b[j], acc[i][j]);
        }
        __syncthreads();
    }

    #pragma unroll
    for (int i = 0; i < 8; i++) {
        const int m = row0 + ty * 8 + i;
        #pragma unroll
        for (int j = 0; j < 8; j++) {
            const int n = col0 + tx * 8 + j;
            const float r = acc[i][j] + bo[n];
            out[(size_t)m * EMBD + n] = fmaxf(r, 0.0f);
        }
    }
}

// ---------------------------------------------------------------------------
#define ATTN_SMEM_BYTES ((4 * 64 * QP + 3 * 64) * (int)sizeof(float))

extern "C" void kernel_launch(void* const* d_in, const int* in_sizes, int n_in,
                              void* d_out, int out_size)
{
    const float* Xk = (const float*)d_in[0];  // inputs_for_keys
    const float* Xv = (const float*)d_in[1];  // inputs_for_values
    const float* Xq = (const float*)d_in[2];  // inputs_for_queries
    const float* Wk = (const float*)d_in[3];
    const float* Wv = (const float*)d_in[4];
    const float* Wq = (const float*)d_in[5];
    const float* Wo = (const float*)d_in[6];
    const float* bo = (const float*)d_in[7];
    float* out = (float*)d_out;

    cudaFuncSetAttribute(attn_kernel,
                         cudaFuncAttributeMaxDynamicSharedMemorySize,
                         ATTN_SMEM_BYTES);

    // 1) QKV projections: 3 GEMMs of [4096x1024] x [1024x1024]
    proj_kernel<<<dim3(32, 8, 3), 256>>>(Xk, Xv, Xq, Wk, Wv, Wq);
    // 2) causal attention, 64 bh-pairs x 16 q-tiles
    attn_kernel<<<dim3(BH, 16), 256, ATTN_SMEM_BYTES>>>();
    // 3) output projection + bias + relu
    out_kernel<<<dim3(32, 8), 256>>>(Wo, bo, out);
}

// round 3
// speedup vs baseline: 1.3827x; 1.3827x over previous
#include <cuda_runtime.h>
#include <cstdint>

// Problem constants
#define BNUM 4
#define SEQ  1024
#define EMBD 1024
#define NH   16
#define HD   64
#define BH   (BNUM * NH)
#define ATT_SCALE (1.0f / 32.0f)   // 1/sqrt(1024), applied to (logits+mask)
#define NEG_INF __int_as_float(0xff800000)

// Scratch (allocation-free contract: __device__ globals)
__device__ float g_q[BH * SEQ * HD];
__device__ float g_k[BH * SEQ * HD];
__device__ float g_v[BH * SEQ * HD];
__device__ float g_ctx[BNUM * SEQ * EMBD];
// Transposed (B = [N,K] K-major) weights, pre-rounded to tf32
__device__ float g_wT[3 * EMBD * EMBD];   // k/v/q
__device__ float g_woT[EMBD * EMBD];

__device__ __forceinline__ float to_tf32(float x) {
    float y; asm("cvt.rna.tf32.f32 %0, %1;" : "=f"(y) : "f"(x)); return y;
}

__device__ __forceinline__ void mma_m16n8k8(float (&d)[4], const uint32_t (&a)[4],
                                            const uint32_t (&b)[2]) {
    asm volatile(
        "mma.sync.aligned.m16n8k8.row.col.f32.tf32.tf32.f32 "
        "{%0,%1,%2,%3}, {%4,%5,%6,%7}, {%8,%9}, {%0,%1,%2,%3};"
        : "+f"(d[0]), "+f"(d[1]), "+f"(d[2]), "+f"(d[3])
        : "r"(a[0]), "r"(a[1]), "r"(a[2]), "r"(a[3]), "r"(b[0]), "r"(b[1]));
}

// ---------------------------------------------------------------------------
// tf32 tensor-core GEMM: C[128x128 tile] = A[M,K] @ Bt[N,K]^T, K=1024.
// BK=32, 256 threads = 8 warps (4x2), warp tile 32x64 (2x8 m16n8k8).
// Double-buffered SMEM, k-major layout with xor swizzle (conflict-free).
// ---------------------------------------------------------------------------
#define APITCH 136
#define ABUF   (32 * APITCH)          // floats per A/B buffer
#define GEMM_SMEM (4 * ABUF * 4)      // bytes: As0,As1,Bs0,Bs1

__device__ __forceinline__ int swz(int k, int m) {
    return k * APITCH + (m ^ (((k >> 2) & 7) << 2));
}

__device__ __forceinline__ void gemm_tf32(const float* __restrict__ A,
                                          const float* __restrict__ Bt,
                                          float* sm, float (&c)[2][8][4])
{
    const int tid  = threadIdx.x;
    const int lane = tid & 31;
    const int warp = tid >> 5;
    const int wm0  = (warp & 3) * 32;
    const int wn0  = (warp >> 2) * 64;
    const int g    = lane >> 2;
    const int tg   = lane & 3;
    const int m0   = blockIdx.x * 128;
    const int n0   = blockIdx.y * 128;

    float* Asb[2] = { sm,            sm + ABUF };
    float* Bsb[2] = { sm + 2 * ABUF, sm + 3 * ABUF };

    const int lrow = tid >> 3;        // base loader row (idx = i*256+tid -> r = idx>>3)
    const int lkq  = tid & 7;

    float4 va[4], vb[4];
    auto ldg = [&](int k0) {
        #pragma unroll
        for (int i = 0; i < 4; i++) {
            const int r = i * 32 + lrow;
            va[i] = *(const float4*)(A  + (size_t)(m0 + r) * EMBD + k0 + lkq * 4);
            vb[i] = *(const float4*)(Bt + (size_t)(n0 + r) * EMBD + k0 + lkq * 4);
        }
    };
    auto sts = [&](int buf) {
        float* ap = Asb[buf];
        float* bp = Bsb[buf];
        #pragma unroll
        for (int i = 0; i < 4; i++) {
            const int r = i * 32 + lrow;
            const float a4[4] = { va[i].x, va[i].y, va[i].z, va[i].w };
            const float b4[4] = { vb[i].x, vb[i].y, vb[i].z, vb[i].w };
            #pragma unroll
            for (int j = 0; j < 4; j++) {
                ap[swz(lkq * 4 + j, r)] = to_tf32(a4[j]);
                bp[swz(lkq * 4 + j, r)] = b4[j];   // Bt pre-rounded
            }
        }
    };

    ldg(0);
    sts(0);
    __syncthreads();

    for (int ch = 0; ch < 32; ch++) {
        const int cur = ch & 1;
        if (ch + 1 < 32) ldg((ch + 1) * 32);

        const float* Ac = Asb[cur];
        const float* Bc = Bsb[cur];
        #pragma unroll
        for (int ks = 0; ks < 4; ks++) {
            const int kk = ks * 8;
            uint32_t af[2][4], bf[8][2];
            #pragma unroll
            for (int mi = 0; mi < 2; mi++) {
                const int mr = wm0 + mi * 16 + g;
                af[mi][0] = __float_as_uint(Ac[swz(kk + tg,     mr)]);
                af[mi][1] = __float_as_uint(Ac[swz(kk + tg,     mr + 8)]);
                af[mi][2] = __float_as_uint(Ac[swz(kk + tg + 4, mr)]);
                af[mi][3] = __float_as_uint(Ac[swz(kk + tg + 4, mr + 8)]);
            }
            #pragma unroll
            for (int ni = 0; ni < 8; ni++) {
                const int nc = wn0 + ni * 8 + g;
                bf[ni][0] = __float_as_uint(Bc[swz(kk + tg,     nc)]);
                bf[ni][1] = __float_as_uint(Bc[swz(kk + tg + 4, nc)]);
            }
            #pragma unroll
            for (int mi = 0; mi < 2; mi++)
                #pragma unroll
                for (int ni = 0; ni < 8; ni++)
                    mma_m16n8k8(c[mi][ni], af[mi], bf[ni]);
        }

        if (ch + 1 < 32) sts((ch + 1) & 1);
        __syncthreads();
    }
}

// Projection: A = X (4096x1024), Bt = g_wT[z], Out scattered into [bh][s][d]
__global__ __launch_bounds__(256, 1) void proj_tc(const float* __restrict__ Xk,
                                                  const float* __restrict__ Xv,
                                                  const float* __restrict__ Xq)
{
    extern __shared__ float smf[];
    const int z = blockIdx.z;
    const float* A  = (z == 0) ? Xk : (z == 1) ? Xv : Xq;
    const float* Bt = g_wT + (size_t)z * EMBD * EMBD;
    float* Out      = (z == 0) ? g_k : (z == 1) ? g_v : g_q;

    float c[2][8][4] = {};
    gemm_tf32(A, Bt, smf, c);

    const int tid = threadIdx.x;
    const int lane = tid & 31, warp = tid >> 5;
    const int wm0 = (warp & 3) * 32, wn0 = (warp >> 2) * 64;
    const int g = lane >> 2, tg = lane & 3;
    const int m0 = blockIdx.x * 128, n0 = blockIdx.y * 128;

    #pragma unroll
    for (int mi = 0; mi < 2; mi++) {
        #pragma unroll
        for (int ni = 0; ni < 8; ni++) {
            const int n = n0 + wn0 + ni * 8 + tg * 2;
            const int h = n >> 6, d = n & 63;
            #pragma unroll
            for (int half = 0; half < 2; half++) {
                const int m = m0 + wm0 + mi * 16 + g + half * 8;
                const int b = m >> 10, s = m & 1023;
                float2 v = make_float2(c[mi][ni][half * 2], c[mi][ni][half * 2 + 1]);
                *(float2*)&Out[((size_t)(b * NH + h) * SEQ + s) * HD + d] = v;
            }
        }
    }
}

// Output projection: A = g_ctx, Bt = g_woT, bias + relu, row-major out
__global__ __launch_bounds__(256, 1) void outproj_tc(const float* __restrict__ bo,
                                                     float* __restrict__ out)
{
    extern __shared__ float smf[];
    float c[2][8][4] = {};
    gemm_tf32(g_ctx, g_woT, smf, c);

    const int tid = threadIdx.x;
    const int lane = tid & 31, warp = tid >> 5;
    const int wm0 = (warp & 3) * 32, wn0 = (warp >> 2) * 64;
    const int g = lane >> 2, tg = lane & 3;
    const int m0 = blockIdx.x * 128, n0 = blockIdx.y * 128;

    #pragma unroll
    for (int mi = 0; mi < 2; mi++) {
        #pragma unroll
        for (int ni = 0; ni < 8; ni++) {
            const int n = n0 + wn0 + ni * 8 + tg * 2;
            const float b0 = bo[n], b1 = bo[n + 1];
            #pragma unroll
            for (int half = 0; half < 2; half++) {
                const int m = m0 + wm0 + mi * 16 + g + half * 8;
                float2 v = make_float2(fmaxf(c[mi][ni][half * 2]     + b0, 0.0f),
                                       fmaxf(c[mi][ni][half * 2 + 1] + b1, 0.0f));
                *(float2*)&out[(size_t)m * EMBD + n] = v;
            }
        }
    }
}

// ---------------------------------------------------------------------------
// Weight transposes (once per launch), baking in tf32 rounding.
// ---------------------------------------------------------------------------
__global__ __launch_bounds__(256) void transpose_w(const float* __restrict__ Wk,
                                                   const float* __restrict__ Wv,
                                                   const float* __restrict__ Wq)
{
    __shared__ float sm[32][65];
    const int z = blockIdx.z;
    const float* W = (z == 0) ? Wk : (z == 1) ? Wv : Wq;
    float* WT = g_wT + (size_t)z * EMBD * EMBD;
    const int h = blockIdx.x;
    const int k0 = blockIdx.y * 32;
    const int tid = threadIdx.x;

    for (int idx = tid; idx < 32 * 64; idx += 256) {
        const int r = idx >> 6, d = idx & 63;
        sm[r][d] = to_tf32(W[((size_t)h * EMBD + (k0 + r)) * HD + d]);
    }
    __syncthreads();
    for (int idx = tid; idx < 64 * 32; idx += 256) {
        const int dd = idx >> 5, kk = idx & 31;
        WT[(size_t)(h * HD + dd) * EMBD + k0 + kk] = sm[kk][dd];
    }
}

__global__ __launch_bounds__(256) void transpose_wo(const float* __restrict__ Wo)
{
    __shared__ float sm[32][33];
    const int n0 = blockIdx.x * 32;
    const int k0 = blockIdx.y * 32;
    const int tid = threadIdx.x;

    for (int idx = tid; idx < 1024; idx += 256) {
        const int r = idx >> 5, c = idx & 31;   // r=k, c=n
        sm[r][c] = to_tf32(Wo[(size_t)(k0 + r) * EMBD + n0 + c]);
    }
    __syncthreads();
    for (int idx = tid; idx < 1024; idx += 256) {
        const int rr = idx >> 5, cc = idx & 31; // rr=n, cc=k
        g_woT[(size_t)(n0 + rr) * EMBD + k0 + cc] = sm[cc][rr];
    }
}

// ---------------------------------------------------------------------------
// Flash-style causal attention (fp32 CUDA-core, unchanged from R1).
// ---------------------------------------------------------------------------
#define QP 65

__global__ __launch_bounds__(256) void attn_kernel()
{
    extern __shared__ float smf[];
    float* Qs   = smf;
    float* Ks   = Qs + 64 * QP;
    float* Vs   = Ks + 64 * QP;
    float* Ss   = Vs + 64 * QP;
    float* mrow = Ss + 64 * QP;
    float* lrow = mrow + 64;
    float* arow = lrow + 64;

    const int bh = blockIdx.x;
    const int qt = blockIdx.y;
    const int q0 = qt * 64;
    const int tid = threadIdx.x;
    const int tx = tid & 15;
    const int ty = tid >> 4;

    const float* Qg = g_q + (size_t)bh * SEQ * HD;
    const float* Kg = g_k + (size_t)bh * SEQ * HD;
    const float* Vg = g_v + (size_t)bh * SEQ * HD;

    for (int idx = tid; idx < 64 * 64; idx += 256) {
        const int r = idx >> 6;
        const int d = idx & 63;
        Qs[r * QP + d] = Qg[(size_t)(q0 + r) * HD + d];
    }
    if (tid < 64) { mrow[tid] = NEG_INF; lrow[tid] = 0.0f; }

    float o[4][4] = {};

    for (int kt = 0; kt <= qt; kt++) {
        const int k0 = kt * 64;
        for (int idx = tid; idx < 64 * 64; idx += 256) {
            const int r = idx >> 6;
            const int d = idx & 63;
            Ks[r * QP + d] = Kg[(size_t)(k0 + r) * HD + d];
            Vs[r * QP + d] = Vg[(size_t)(k0 + r) * HD + d];
        }
        __syncthreads();

        float sacc[4][4] = {};
        #pragma unroll 8
        for (int d = 0; d < 64; d++) {
            float a[4], b[4];
            #pragma unroll
            for (int i = 0; i < 4; i++) a[i] = Qs[(ty * 4 + i) * QP + d];
            #pragma unroll
            for (int j = 0; j < 4; j++) b[j] = Ks[(tx * 4 + j) * QP + d];
            #pragma unroll
            for (int i = 0; i < 4; i++)
                #pragma unroll
                for (int j = 0; j < 4; j++)
                    sacc[i][j] = fmaf(a[i], b[j], sacc[i][j]);
        }

        const bool diag = (kt == qt);
        #pragma unroll
        for (int i = 0; i < 4; i++) {
            const int q = q0 + ty * 4 + i;
            #pragma unroll
            for (int j = 0; j < 4; j++) {
                const int k = k0 + tx * 4 + j;
                float v = sacc[i][j] * ATT_SCALE;
                if (diag && k > q) v = NEG_INF;
                Ss[(ty * 4 + i) * QP + (tx * 4 + j)] = v;
            }
        }
        __syncthreads();

        if (tid < 64) {
            const int r = tid;
            const float mold = mrow[r];
            float mx = mold;
            #pragma unroll 8
            for (int j = 0; j < 64; j++) mx = fmaxf(mx, Ss[r * QP + j]);
            const float al = __expf(mold - mx);
            float sum = 0.0f;
            #pragma unroll 8
            for (int j = 0; j < 64; j++) {
                const float p = __expf(Ss[r * QP + j] - mx);
                Ss[r * QP + j] = p;
                sum += p;
            }
            mrow[r] = mx;
            lrow[r] = lrow[r] * al + sum;
            arow[r] = al;
        }
        __syncthreads();

        float al[4];
        #pragma unroll
        for (int i = 0; i < 4; i++) {
            al[i] = arow[ty * 4 + i];
            #pragma unroll
            for (int jj = 0; jj < 4; jj++) o[i][jj] *= al[i];
        }
        #pragma unroll 8
        for (int j = 0; j < 64; j++) {
            float p[4], v[4];
            #pragma unroll
            for (int i = 0; i < 4; i++) p[i] = Ss[(ty * 4 + i) * QP + j];
            #pragma unroll
            for (int jj = 0; jj < 4; jj++) v[jj] = Vs[j * QP + (tx * 4 + jj)];
            #pragma unroll
            for (int i = 0; i < 4; i++)
                #pragma unroll
                for (int jj = 0; jj < 4; jj++)
                    o[i][jj] = fmaf(p[i], v[jj], o[i][jj]);
        }
        __syncthreads();
    }

    const int b = bh >> 4;
    const int h = bh & 15;
    #pragma unroll
    for (int i = 0; i < 4; i++) {
        const int q = q0 + ty * 4 + i;
        const float linv = 1.0f / lrow[ty * 4 + i];
        #pragma unroll
        for (int jj = 0; jj < 4; jj++) {
            const int d = tx * 4 + jj;
            g_ctx[(size_t)(b * SEQ + q) * EMBD + h * 64 + d] = o[i][jj] * linv;
        }
    }
}

// ---------------------------------------------------------------------------
#define ATTN_SMEM_BYTES ((4 * 64 * QP + 3 * 64) * (int)sizeof(float))

extern "C" void kernel_launch(void* const* d_in, const int* in_sizes, int n_in,
                              void* d_out, int out_size)
{
    const float* Xk = (const float*)d_in[0];
    const float* Xv = (const float*)d_in[1];
    const float* Xq = (const float*)d_in[2];
    const float* Wk = (const float*)d_in[3];
    const float* Wv = (const float*)d_in[4];
    const float* Wq = (const float*)d_in[5];
    const float* Wo = (const float*)d_in[6];
    const float* bo = (const float*)d_in[7];
    float* out = (float*)d_out;

    cudaFuncSetAttribute(proj_tc, cudaFuncAttributeMaxDynamicSharedMemorySize, GEMM_SMEM);
    cudaFuncSetAttribute(outproj_tc, cudaFuncAttributeMaxDynamicSharedMemorySize, GEMM_SMEM);
    cudaFuncSetAttribute(attn_kernel, cudaFuncAttributeMaxDynamicSharedMemorySize, ATTN_SMEM_BYTES);

    // 0) transpose weights to [N,K] K-major, tf32-rounded
    transpose_w<<<dim3(NH, 32, 3), 256>>>(Wk, Wv, Wq);
    transpose_wo<<<dim3(32, 32), 256>>>(Wo);
    // 1) QKV projections on tensor cores (mma.sync tf32)
    proj_tc<<<dim3(32, 8, 3), 256, GEMM_SMEM>>>(Xk, Xv, Xq);
    // 2) causal attention (fp32 CUDA-core, next optimization target)
    attn_kernel<<<dim3(BH, 16), 256, ATTN_SMEM_BYTES>>>();
    // 3) output projection + bias + relu on tensor cores
    outproj_tc<<<dim3(32, 8), 256, GEMM_SMEM>>>(bo, out);
}

// round 4
// speedup vs baseline: 1.8782x; 1.3583x over previous
#include <cuda_runtime.h>
#include <cstdint>

// Problem constants
#define BNUM 4
#define SEQ  1024
#define EMBD 1024
#define NH   16
#define HD   64
#define BH   (BNUM * NH)
#define ATT_SCALE (1.0f / 32.0f)   // 1/sqrt(1024), applied to (logits+mask)
#define NEG_INF __int_as_float(0xff800000)

// Scratch (allocation-free contract: __device__ globals)
__device__ float g_q[BH * SEQ * HD];          // [bh][s][d], tf32-rounded
__device__ float g_k[BH * SEQ * HD];          // [bh][s][d], tf32-rounded
__device__ float g_vT[BH * HD * SEQ];         // [bh][d][s], tf32-rounded
__device__ float g_ctx[BNUM * SEQ * EMBD];    // fp32
// Transposed (B = [N,K] K-major) weights, pre-rounded to tf32
__device__ float g_wT[3 * EMBD * EMBD];       // k/v/q
__device__ float g_woT[EMBD * EMBD];

__device__ __forceinline__ float to_tf32(float x) {
    float y; asm("cvt.rna.tf32.f32 %0, %1;" : "=f"(y) : "f"(x)); return y;
}

__device__ __forceinline__ void mma_m16n8k8(float (&d)[4], const uint32_t (&a)[4],
                                            const uint32_t (&b)[2]) {
    asm volatile(
        "mma.sync.aligned.m16n8k8.row.col.f32.tf32.tf32.f32 "
        "{%0,%1,%2,%3}, {%4,%5,%6,%7}, {%8,%9}, {%0,%1,%2,%3};"
        : "+f"(d[0]), "+f"(d[1]), "+f"(d[2]), "+f"(d[3])
        : "r"(a[0]), "r"(a[1]), "r"(a[2]), "r"(a[3]), "r"(b[0]), "r"(b[1]));
}

// ---------------------------------------------------------------------------
// tf32 tensor-core GEMM: C[128x128 tile] = A[M,K] @ Bt[N,K]^T, K=1024.
// BK=32, 256 threads = 8 warps (4x2), warp tile 32x64 (2x8 m16n8k8).
// ---------------------------------------------------------------------------
#define APITCH 136
#define ABUF   (32 * APITCH)
#define GEMM_SMEM (4 * ABUF * 4)

__device__ __forceinline__ int swz(int k, int m) {
    return k * APITCH + (m ^ (((k >> 2) & 7) << 2));
}

__device__ __forceinline__ void gemm_tf32(const float* __restrict__ A,
                                          const float* __restrict__ Bt,
                                          float* sm, float (&c)[2][8][4])
{
    const int tid  = threadIdx.x;
    const int lane = tid & 31;
    const int warp = tid >> 5;
    const int wm0  = (warp & 3) * 32;
    const int wn0  = (warp >> 2) * 64;
    const int g    = lane >> 2;
    const int tg   = lane & 3;
    const int m0   = blockIdx.x * 128;
    const int n0   = blockIdx.y * 128;

    float* Asb[2] = { sm,            sm + ABUF };
    float* Bsb[2] = { sm + 2 * ABUF, sm + 3 * ABUF };

    const int lrow = tid >> 3;
    const int lkq  = tid & 7;

    float4 va[4], vb[4];
    auto ldg = [&](int k0) {
        #pragma unroll
        for (int i = 0; i < 4; i++) {
            const int r = i * 32 + lrow;
            va[i] = *(const float4*)(A  + (size_t)(m0 + r) * EMBD + k0 + lkq * 4);
            vb[i] = *(const float4*)(Bt + (size_t)(n0 + r) * EMBD + k0 + lkq * 4);
        }
    };
    auto sts = [&](int buf) {
        float* ap = Asb[buf];
        float* bp = Bsb[buf];
        #pragma unroll
        for (int i = 0; i < 4; i++) {
            const int r = i * 32 + lrow;
            const float a4[4] = { va[i].x, va[i].y, va[i].z, va[i].w };
            const float b4[4] = { vb[i].x, vb[i].y, vb[i].z, vb[i].w };
            #pragma unroll
            for (int j = 0; j < 4; j++) {
                ap[swz(lkq * 4 + j, r)] = to_tf32(a4[j]);
                bp[swz(lkq * 4 + j, r)] = b4[j];
            }
        }
    };

    ldg(0);
    sts(0);
    __syncthreads();

    for (int ch = 0; ch < 32; ch++) {
        const int cur = ch & 1;
        if (ch + 1 < 32) ldg((ch + 1) * 32);

        const float* Ac = Asb[cur];
        const float* Bc = Bsb[cur];
        #pragma unroll
        for (int ks = 0; ks < 4; ks++) {
            const int kk = ks * 8;
            uint32_t af[2][4], bf[8][2];
            #pragma unroll
            for (int mi = 0; mi < 2; mi++) {
                const int mr = wm0 + mi * 16 + g;
                af[mi][0] = __float_as_uint(Ac[swz(kk + tg,     mr)]);
                af[mi][1] = __float_as_uint(Ac[swz(kk + tg,     mr + 8)]);
                af[mi][2] = __float_as_uint(Ac[swz(kk + tg + 4, mr)]);
                af[mi][3] = __float_as_uint(Ac[swz(kk + tg + 4, mr + 8)]);
            }
            #pragma unroll
            for (int ni = 0; ni < 8; ni++) {
                const int nc = wn0 + ni * 8 + g;
                bf[ni][0] = __float_as_uint(Bc[swz(kk + tg,     nc)]);
                bf[ni][1] = __float_as_uint(Bc[swz(kk + tg + 4, nc)]);
            }
            #pragma unroll
            for (int mi = 0; mi < 2; mi++)
                #pragma unroll
                for (int ni = 0; ni < 8; ni++)
                    mma_m16n8k8(c[mi][ni], af[mi], bf[ni]);
        }

        if (ch + 1 < 32) sts((ch + 1) & 1);
        __syncthreads();
    }
}

// Projection: outputs tf32-rounded Q/K (as [bh][s][d]) and V transposed [bh][d][s]
__global__ __launch_bounds__(256, 1) void proj_tc(const float* __restrict__ Xk,
                                                  const float* __restrict__ Xv,
                                                  const float* __restrict__ Xq)
{
    extern __shared__ float smf[];
    const int z = blockIdx.z;
    const float* A  = (z == 0) ? Xk : (z == 1) ? Xv : Xq;
    const float* Bt = g_wT + (size_t)z * EMBD * EMBD;

    float c[2][8][4] = {};
    gemm_tf32(A, Bt, smf, c);

    const int tid = threadIdx.x;
    const int lane = tid & 31, warp = tid >> 5;
    const int wm0 = (warp & 3) * 32, wn0 = (warp >> 2) * 64;
    const int g = lane >> 2, tg = lane & 3;
    const int m0 = blockIdx.x * 128, n0 = blockIdx.y * 128;

    if (z == 1) {
        // V -> g_vT [bh][d][s]
        #pragma unroll
        for (int mi = 0; mi < 2; mi++) {
            #pragma unroll
            for (int ni = 0; ni < 8; ni++) {
                const int n = n0 + wn0 + ni * 8 + tg * 2;
                const int h = n >> 6, d = n & 63;
                #pragma unroll
                for (int half = 0; half < 2; half++) {
                    const int m = m0 + wm0 + mi * 16 + g + half * 8;
                    const int b = m >> 10, s = m & 1023;
                    const size_t base = (size_t)(b * NH + h) * HD;
                    g_vT[(base + d)     * SEQ + s] = to_tf32(c[mi][ni][half * 2]);
                    g_vT[(base + d + 1) * SEQ + s] = to_tf32(c[mi][ni][half * 2 + 1]);
                }
            }
        }
    } else {
        float* Out = (z == 0) ? g_k : g_q;
        #pragma unroll
        for (int mi = 0; mi < 2; mi++) {
            #pragma unroll
            for (int ni = 0; ni < 8; ni++) {
                const int n = n0 + wn0 + ni * 8 + tg * 2;
                const int h = n >> 6, d = n & 63;
                #pragma unroll
                for (int half = 0; half < 2; half++) {
                    const int m = m0 + wm0 + mi * 16 + g + half * 8;
                    const int b = m >> 10, s = m & 1023;
                    float2 v = make_float2(to_tf32(c[mi][ni][half * 2]),
                                           to_tf32(c[mi][ni][half * 2 + 1]));
                    *(float2*)&Out[((size_t)(b * NH + h) * SEQ + s) * HD + d] = v;
                }
            }
        }
    }
}

// Output projection: A = g_ctx, Bt = g_woT, bias + relu, row-major out
__global__ __launch_bounds__(256, 1) void outproj_tc(const float* __restrict__ bo,
                                                     float* __restrict__ out)
{
    extern __shared__ float smf[];
    float c[2][8][4] = {};
    gemm_tf32(g_ctx, g_woT, smf, c);

    const int tid = threadIdx.x;
    const int lane = tid & 31, warp = tid >> 5;
    const int wm0 = (warp & 3) * 32, wn0 = (warp >> 2) * 64;
    const int g = lane >> 2, tg = lane & 3;
    const int m0 = blockIdx.x * 128, n0 = blockIdx.y * 128;

    #pragma unroll
    for (int mi = 0; mi < 2; mi++) {
        #pragma unroll
        for (int ni = 0; ni < 8; ni++) {
            const int n = n0 + wn0 + ni * 8 + tg * 2;
            const float b0 = bo[n], b1 = bo[n + 1];
            #pragma unroll
            for (int half = 0; half < 2; half++) {
                const int m = m0 + wm0 + mi * 16 + g + half * 8;
                float2 v = make_float2(fmaxf(c[mi][ni][half * 2]     + b0, 0.0f),
                                       fmaxf(c[mi][ni][half * 2 + 1] + b1, 0.0f));
                *(float2*)&out[(size_t)m * EMBD + n] = v;
            }
        }
    }
}

// ---------------------------------------------------------------------------
// Weight transposes (once per launch), baking in tf32 rounding.
// ---------------------------------------------------------------------------
__global__ __launch_bounds__(256) void transpose_w(const float* __restrict__ Wk,
                                                   const float* __restrict__ Wv,
                                                   const float* __restrict__ Wq)
{
    __shared__ float sm[32][65];
    const int z = blockIdx.z;
    const float* W = (z == 0) ? Wk : (z == 1) ? Wv : Wq;
    float* WT = g_wT + (size_t)z * EMBD * EMBD;
    const int h = blockIdx.x;
    const int k0 = blockIdx.y * 32;
    const int tid = threadIdx.x;

    for (int idx = tid; idx < 32 * 64; idx += 256) {
        const int r = idx >> 6, d = idx & 63;
        sm[r][d] = to_tf32(W[((size_t)h * EMBD + (k0 + r)) * HD + d]);
    }
    __syncthreads();
    for (int idx = tid; idx < 64 * 32; idx += 256) {
        const int dd = idx >> 5, kk = idx & 31;
        WT[(size_t)(h * HD + dd) * EMBD + k0 + kk] = sm[kk][dd];
    }
}

__global__ __launch_bounds__(256) void transpose_wo(const float* __restrict__ Wo)
{
    __shared__ float sm[32][33];
    const int n0 = blockIdx.x * 32;
    const int k0 = blockIdx.y * 32;
    const int tid = threadIdx.x;

    for (int idx = tid; idx < 1024; idx += 256) {
        const int r = idx >> 5, c = idx & 31;
        sm[r][c] = to_tf32(Wo[(size_t)(k0 + r) * EMBD + n0 + c]);
    }
    __syncthreads();
    for (int idx = tid; idx < 1024; idx += 256) {
        const int rr = idx >> 5, cc = idx & 31;
        g_woT[(size_t)(n0 + rr) * EMBD + k0 + cc] = sm[cc][rr];
    }
}

// ---------------------------------------------------------------------------
// Tensor-core flash attention.
// Block = (bh, 128-q tile). 8 warps x 16 q-rows. Key tiles of 64.
// S = Q K^T (mma tf32, Q frags register-resident), online softmax (fp32),
// P routed via warp-private SMEM (tf32), O += P V (mma tf32, V^T from g_vT).
// ---------------------------------------------------------------------------
#define KP 68
#define ATTN_SMEM ((2 * 64 * KP + 8 * 16 * KP) * (int)sizeof(float))

__global__ __launch_bounds__(256, 1) void attn_tc()
{
    extern __shared__ float smf[];
    float* Ks = smf;               // [64 keys][KP d]
    float* Vt = Ks + 64 * KP;      // [64 d][KP keys]
    float* Ps = Vt + 64 * KP;      // [8 warps][16 q][KP keys]

    const int bh = blockIdx.x;
    const int qt = 7 - blockIdx.y;        // heavy tiles first
    const int q0 = qt * 128;
    const int tid = threadIdx.x, lane = tid & 31, warp = tid >> 5;
    const int g = lane >> 2, tg = lane & 3;
    const int wq = q0 + warp * 16;

    const float* Qg = g_q  + (size_t)bh * SEQ * HD;
    const float* Kg = g_k  + (size_t)bh * SEQ * HD;
    const float* Vg = g_vT + (size_t)bh * HD * SEQ;
    float* Pw = Ps + warp * 16 * KP;

    // Q fragments for the whole block (16 x 64, 8 k-steps)
    uint32_t aq[8][4];
    #pragma unroll
    for (int kk = 0; kk < 8; kk++) {
        aq[kk][0] = __float_as_uint(Qg[(size_t)(wq + g)     * HD + kk * 8 + tg]);
        aq[kk][1] = __float_as_uint(Qg[(size_t)(wq + g + 8) * HD + kk * 8 + tg]);
        aq[kk][2] = __float_as_uint(Qg[(size_t)(wq + g)     * HD + kk * 8 + tg + 4]);
        aq[kk][3] = __float_as_uint(Qg[(size_t)(wq + g + 8) * HD + kk * 8 + tg + 4]);
    }

    float o[8][4] = {};
    float m_r[2] = { NEG_INF, NEG_INF };
    float l_r[2] = { 0.0f, 0.0f };

    const int ktend = 2 * qt + 2;
    for (int kt = 0; kt < ktend; kt++) {
        const int k0 = kt * 64;

        // cooperative loads: K tile [key][d], V^T tile [d][key]
        #pragma unroll
        for (int i = 0; i < 4; i++) {
            const int idx = i * 256 + tid;
            const int r = idx >> 4, c4 = (idx & 15) * 4;
            *(float4*)&Ks[r * KP + c4] = *(const float4*)(Kg + (size_t)(k0 + r) * HD + c4);
            *(float4*)&Vt[r * KP + c4] = *(const float4*)(Vg + (size_t)r * SEQ + k0 + c4);
        }
        __syncthreads();

        // S = Q K^T
        float cs[8][4] = {};
        #pragma unroll
        for (int kk = 0; kk < 8; kk++) {
            uint32_t bf[8][2];
            #pragma unroll
            for (int ni = 0; ni < 8; ni++) {
                bf[ni][0] = __float_as_uint(Ks[(ni * 8 + g) * KP + kk * 8 + tg]);
                bf[ni][1] = __float_as_uint(Ks[(ni * 8 + g) * KP + kk * 8 + tg + 4]);
            }
            #pragma unroll
            for (int ni = 0; ni < 8; ni++)
                mma_m16n8k8(cs[ni], aq[kk], bf[ni]);
        }

        // scale + causal mask (only last two key tiles can cross the diagonal)
        const bool msk = (kt >= 2 * qt);
        #pragma unroll
        for (int ni = 0; ni < 8; ni++) {
            #pragma unroll
            for (int e = 0; e < 4; e++) {
                float s = cs[ni][e] * ATT_SCALE;
                if (msk) {
                    const int q = wq + g + ((e >> 1) << 3);
                    const int k = k0 + ni * 8 + tg * 2 + (e & 1);
                    if (k > q) s = NEG_INF;
                }
                cs[ni][e] = s;
            }
        }

        // online softmax (rows g and g+8), quad reductions
        #pragma unroll
        for (int hh = 0; hh < 2; hh++) {
            float mx = NEG_INF;
            #pragma unroll
            for (int ni = 0; ni < 8; ni++)
                mx = fmaxf(mx, fmaxf(cs[ni][2 * hh], cs[ni][2 * hh + 1]));
            mx = fmaxf(mx, __shfl_xor_sync(0xffffffff, mx, 1));
            mx = fmaxf(mx, __shfl_xor_sync(0xffffffff, mx, 2));
            const float mnew = fmaxf(m_r[hh], mx);
            const float alpha = __expf(m_r[hh] - mnew);
            float sum = 0.0f;
            #pragma unroll
            for (int ni = 0; ni < 8; ni++) {
                const float p0 = __expf(cs[ni][2 * hh]     - mnew);
                const float p1 = __expf(cs[ni][2 * hh + 1] - mnew);
                cs[ni][2 * hh] = p0; cs[ni][2 * hh + 1] = p1;
                sum += p0 + p1;
            }
            sum += __shfl_xor_sync(0xffffffff, sum, 1);
            sum += __shfl_xor_sync(0xffffffff, sum, 2);
            l_r[hh] = l_r[hh] * alpha + sum;
            m_r[hh] = mnew;
            #pragma unroll
            for (int ni = 0; ni < 8; ni++) {
                o[ni][2 * hh] *= alpha; o[ni][2 * hh + 1] *= alpha;
            }
        }

        // P -> warp-private SMEM (tf32)
        #pragma unroll
        for (int ni = 0; ni < 8; ni++) {
            Pw[g * KP + ni * 8 + tg * 2]           = to_tf32(cs[ni][0]);
            Pw[g * KP + ni * 8 + tg * 2 + 1]       = to_tf32(cs[ni][1]);
            Pw[(g + 8) * KP + ni * 8 + tg * 2]     = to_tf32(cs[ni][2]);
            Pw[(g + 8) * KP + ni * 8 + tg * 2 + 1] = to_tf32(cs[ni][3]);
        }
        __syncwarp();

        // O += P V   (contract over 64 keys; B = V^T[d][key])
        #pragma unroll
        for (int kk = 0; kk < 8; kk++) {
            uint32_t ap[4];
            ap[0] = __float_as_uint(Pw[g * KP + kk * 8 + tg]);
            ap[1] = __float_as_uint(Pw[(g + 8) * KP + kk * 8 + tg]);
            ap[2] = __float_as_uint(Pw[g * KP + kk * 8 + tg + 4]);
            ap[3] = __float_as_uint(Pw[(g + 8) * KP + kk * 8 + tg + 4]);
            uint32_t bv[8][2];
            #pragma unroll
            for (int ni = 0; ni < 8; ni++) {
                bv[ni][0] = __float_as_uint(Vt[(ni * 8 + g) * KP + kk * 8 + tg]);
                bv[ni][1] = __float_as_uint(Vt[(ni * 8 + g) * KP + kk * 8 + tg + 4]);
            }
            #pragma unroll
            for (int ni = 0; ni < 8; ni++)
                mma_m16n8k8(o[ni], ap, bv[ni]);
        }
        __syncthreads();
    }

    // epilogue: normalize and write concat ctx
    const int b = bh >> 4;
    const int h4 = bh & 15;
    const float inv0 = 1.0f / l_r[0];
    const float inv1 = 1.0f / l_r[1];
    #pragma unroll
    for (int ni = 0; ni < 8; ni++) {
        const int d = h4 * 64 + ni * 8 + tg * 2;
        const int r0 = wq + g, r1 = wq + g + 8;
        *(float2*)&g_ctx[(size_t)(b * SEQ + r0) * EMBD + d] =
            make_float2(o[ni][0] * inv0, o[ni][1] * inv0);
        *(float2*)&g_ctx[(size_t)(b * SEQ + r1) * EMBD + d] =
            make_float2(o[ni][2] * inv1, o[ni][3] * inv1);
    }
}

// ---------------------------------------------------------------------------
extern "C" void kernel_launch(void* const* d_in, const int* in_sizes, int n_in,
                              void* d_out, int out_size)
{
    const float* Xk = (const float*)d_in[0];
    const float* Xv = (const float*)d_in[1];
    const float* Xq = (const float*)d_in[2];
    const float* Wk = (const float*)d_in[3];
    const float* Wv = (const float*)d_in[4];
    const float* Wq = (const float*)d_in[5];
    const float* Wo = (const float*)d_in[6];
    const float* bo = (const float*)d_in[7];
    float* out = (float*)d_out;

    cudaFuncSetAttribute(proj_tc, cudaFuncAttributeMaxDynamicSharedMemorySize, GEMM_SMEM);
    cudaFuncSetAttribute(outproj_tc, cudaFuncAttributeMaxDynamicSharedMemorySize, GEMM_SMEM);
    cudaFuncSetAttribute(attn_tc, cudaFuncAttributeMaxDynamicSharedMemorySize, ATTN_SMEM);

    // 0) transpose weights to [N,K] K-major, tf32-rounded
    transpose_w<<<dim3(NH, 32, 3), 256>>>(Wk, Wv, Wq);
    transpose_wo<<<dim3(32, 32), 256>>>(Wo);
    // 1) QKV projections on tensor cores (V written transposed)
    proj_tc<<<dim3(32, 8, 3), 256, GEMM_SMEM>>>(Xk, Xv, Xq);
    // 2) causal flash attention on tensor cores
    attn_tc<<<dim3(BH, 8), 256, ATTN_SMEM>>>();
    // 3) output projection + bias + relu on tensor cores
    outproj_tc<<<dim3(32, 8), 256, GEMM_SMEM>>>(bo, out);
}

// round 5
// speedup vs baseline: 3.4640x; 1.8443x over previous
#include <cuda_runtime.h>
#include <cstdint>

// Problem constants
#define BNUM 4
#define SEQ  1024
#define EMBD 1024
#define NH   16
#define HD   64
#define BH   (BNUM * NH)
#define ATT_SCALE (1.0f / 32.0f)   // 1/sqrt(1024), applied to (logits+mask)
#define NEG_INF __int_as_float(0xff800000)

// Scratch (allocation-free contract: __device__ globals)
__device__ float g_q[BH * SEQ * HD];          // [bh][s][d], tf32-rounded
__device__ float g_k[BH * SEQ * HD];          // [bh][s][d], tf32-rounded
__device__ float g_vT[BH * HD * SEQ];         // [bh][d][s], tf32-rounded
__device__ float g_ctx[BNUM * SEQ * EMBD];    // tf32-rounded (attn epilogue)
__device__ float g_xr[3 * BNUM * SEQ * EMBD]; // tf32-rounded inputs k/v/q
// Transposed (B = [N,K] K-major) weights, pre-rounded to tf32
__device__ float g_wT[3 * EMBD * EMBD];       // k/v/q
__device__ float g_woT[EMBD * EMBD];

__device__ __forceinline__ float to_tf32(float x) {
    float y; asm("cvt.rna.tf32.f32 %0, %1;" : "=f"(y) : "f"(x)); return y;
}
__device__ __forceinline__ uint32_t smem_u32(const void* p) {
    uint32_t a;
    asm("{ .reg .u64 t; cvta.to.shared.u64 t, %1; cvt.u32.u64 %0, t; }"
        : "=r"(a) : "l"(p));
    return a;
}

__device__ __forceinline__ void mma_m16n8k8(float (&d)[4], const uint32_t (&a)[4],
                                            const uint32_t b0, const uint32_t b1) {
    asm volatile(
        "mma.sync.aligned.m16n8k8.row.col.f32.tf32.tf32.f32 "
        "{%0,%1,%2,%3}, {%4,%5,%6,%7}, {%8,%9}, {%0,%1,%2,%3};"
        : "+f"(d[0]), "+f"(d[1]), "+f"(d[2]), "+f"(d[3])
        : "r"(a[0]), "r"(a[1]), "r"(a[2]), "r"(a[3]), "r"(b0), "r"(b1));
}

#define LDMX4(r, addr) \
    asm volatile("ldmatrix.sync.aligned.m8n8.x4.shared.b16 {%0,%1,%2,%3}, [%4];" \
        : "=r"((r)[0]), "=r"((r)[1]), "=r"((r)[2]), "=r"((r)[3]) : "r"(addr))

#define CP16(dst, src) \
    asm volatile("cp.async.cg.shared.global [%0], [%1], 16;" :: "r"(dst), "l"(src))
#define CP_COMMIT() asm volatile("cp.async.commit_group;" ::: "memory")
template<int N> __device__ __forceinline__ void cp_wait() {
    asm volatile("cp.async.wait_group %0;" :: "n"(N) : "memory");
}

// ---------------------------------------------------------------------------
// tf32 tensor-core GEMM: C[128x128] = A[M,K] @ Bt[N,K]^T, K=1024, BK=32.
// 3-stage cp.async pipeline; ldmatrix tf32 fragments; 8 warps, warp tile 64x32.
// smem layout per tile: [row 0..127][chunk 0..7], chunk = 16B, swizzled
// by chunk ^= (row & 7). Conflict-free for cp.async stores and ldmatrix.
// ---------------------------------------------------------------------------
#define TILE_BYTES 16384                // 128 rows * 8 chunks * 16B
#define GEMM_SMEM  (3 * 2 * TILE_BYTES) // 3 stages x (A,B)

__device__ __forceinline__ void gemm_tf32(const float* __restrict__ A,
                                          const float* __restrict__ Bt,
                                          char* sm, float (&c)[4][4][4])
{
    const int tid  = threadIdx.x;
    const int lane = tid & 31;
    const int warp = tid >> 5;
    const int m0   = blockIdx.x * 128;
    const int n0   = blockIdx.y * 128;
    const uint32_t sb = smem_u32(sm);

    auto issue = [&](int stage, int k0) {
        const uint32_t sa  = sb + stage * 2 * TILE_BYTES;
        const uint32_t sbb = sa + TILE_BYTES;
        #pragma unroll
        for (int i = 0; i < 4; i++) {
            const int idx = i * 256 + tid;
            const int row = idx >> 3, ch = idx & 7;
            const uint32_t off = (uint32_t)((row << 3) + (ch ^ (row & 7))) << 4;
            CP16(sa  + off, A  + (size_t)(m0 + row) * EMBD + k0 + ch * 4);
            CP16(sbb + off, Bt + (size_t)(n0 + row) * EMBD + k0 + ch * 4);
        }
        CP_COMMIT();
    };

    issue(0, 0);
    issue(1, 32);

    const int l7   = lane & 7;
    const int wm   = (warp & 1) * 64;
    const int wn   = (warp >> 1) * 32;
    const int aRow = wm + l7 + ((lane >> 3) & 1) * 8;  // + mi*16
    const int aChO = lane >> 4;                        // 0/1 (k lo/hi half)
    const int bRow = wn + l7 + (lane >> 4) * 8;        // + pair*16
    const int bChO = (lane >> 3) & 1;

    for (int ch = 0; ch < 32; ch++) {
        const int st = ch % 3;
        if (ch < 30) cp_wait<1>(); else cp_wait<0>();
        __syncthreads();
        const uint32_t sa  = sb + st * 2 * TILE_BYTES;
        const uint32_t sbb = sa + TILE_BYTES;

        #pragma unroll
        for (int ks = 0; ks < 4; ks++) {
            uint32_t af[4][4], bq[2][4];
            #pragma unroll
            for (int mi = 0; mi < 4; mi++) {
                const int row = aRow + mi * 16;
                const uint32_t addr =
                    sa + ((uint32_t)((row << 3) + ((ks * 2 + aChO) ^ (row & 7))) << 4);
                LDMX4(af[mi], addr);
            }
            #pragma unroll
            for (int p = 0; p < 2; p++) {
                const int row = bRow + p * 16;
                const uint32_t addr =
                    sbb + ((uint32_t)((row << 3) + ((ks * 2 + bChO) ^ (row & 7))) << 4);
                LDMX4(bq[p], addr);
            }
            #pragma unroll
            for (int mi = 0; mi < 4; mi++)
                #pragma unroll
                for (int ni = 0; ni < 4; ni++)
                    mma_m16n8k8(c[mi][ni], af[mi],
                                bq[ni >> 1][(ni & 1) * 2],
                                bq[ni >> 1][(ni & 1) * 2 + 1]);
        }

        if (ch + 2 < 32) issue((ch + 2) % 3, (ch + 2) * 32);
    }
}

// Projection: outputs tf32-rounded Q/K (as [bh][s][d]) and V transposed [bh][d][s]
__global__ __launch_bounds__(256, 1) void proj_tc()
{
    extern __shared__ char smc[];
    const int z = blockIdx.z;
    const float* A  = g_xr + (size_t)z * BNUM * SEQ * EMBD;
    const float* Bt = g_wT + (size_t)z * EMBD * EMBD;

    float c[4][4][4] = {};
    gemm_tf32(A, Bt, smc, c);

    const int tid = threadIdx.x;
    const int lane = tid & 31, warp = tid >> 5;
    const int wm = (warp & 1) * 64, wn = (warp >> 1) * 32;
    const int g = lane >> 2, tg = lane & 3;
    const int m0 = blockIdx.x * 128, n0 = blockIdx.y * 128;

    if (z == 1) {
        // V -> g_vT [bh][d][s]
        #pragma unroll
        for (int mi = 0; mi < 4; mi++) {
            #pragma unroll
            for (int ni = 0; ni < 4; ni++) {
                const int n = n0 + wn + ni * 8 + tg * 2;
                const int h = n >> 6, d = n & 63;
                #pragma unroll
                for (int half = 0; half < 2; half++) {
                    const int m = m0 + wm + mi * 16 + g + half * 8;
                    const int b = m >> 10, s = m & 1023;
                    const size_t base = (size_t)(b * NH + h) * HD;
                    g_vT[(base + d)     * SEQ + s] = to_tf32(c[mi][ni][half * 2]);
                    g_vT[(base + d + 1) * SEQ + s] = to_tf32(c[mi][ni][half * 2 + 1]);
                }
            }
        }
    } else {
        float* Out = (z == 0) ? g_k : g_q;
        #pragma unroll
        for (int mi = 0; mi < 4; mi++) {
            #pragma unroll
            for (int ni = 0; ni < 4; ni++) {
                const int n = n0 + wn + ni * 8 + tg * 2;
                const int h = n >> 6, d = n & 63;
                #pragma unroll
                for (int half = 0; half < 2; half++) {
                    const int m = m0 + wm + mi * 16 + g + half * 8;
                    const int b = m >> 10, s = m & 1023;
                    float2 v = make_float2(to_tf32(c[mi][ni][half * 2]),
                                           to_tf32(c[mi][ni][half * 2 + 1]));
                    *(float2*)&Out[((size_t)(b * NH + h) * SEQ + s) * HD + d] = v;
                }
            }
        }
    }
}

// Output projection: A = g_ctx (tf32-rounded), Bt = g_woT, bias + relu
__global__ __launch_bounds__(256, 1) void outproj_tc(const float* __restrict__ bo,
                                                     float* __restrict__ out)
{
    extern __shared__ char smc[];
    float c[4][4][4] = {};
    gemm_tf32(g_ctx, g_woT, smc, c);

    const int tid = threadIdx.x;
    const int lane = tid & 31, warp = tid >> 5;
    const int wm = (warp & 1) * 64, wn = (warp >> 1) * 32;
    const int g = lane >> 2, tg = lane & 3;
    const int m0 = blockIdx.x * 128, n0 = blockIdx.y * 128;

    #pragma unroll
    for (int mi = 0; mi < 4; mi++) {
        #pragma unroll
        for (int ni = 0; ni < 4; ni++) {
            const int n = n0 + wn + ni * 8 + tg * 2;
            const float b0 = bo[n], b1 = bo[n + 1];
            #pragma unroll
            for (int half = 0; half < 2; half++) {
                const int m = m0 + wm + mi * 16 + g + half * 8;
                float2 v = make_float2(fmaxf(c[mi][ni][half * 2]     + b0, 0.0f),
                                       fmaxf(c[mi][ni][half * 2 + 1] + b1, 0.0f));
                *(float2*)&out[(size_t)m * EMBD + n] = v;
            }
        }
    }
}

// ---------------------------------------------------------------------------
// Input pre-rounding to tf32 (cp.async path cannot convert in-flight)
// ---------------------------------------------------------------------------
__global__ __launch_bounds__(256) void round_inputs(const float* __restrict__ Xk,
                                                    const float* __restrict__ Xv,
                                                    const float* __restrict__ Xq)
{
    const int z = blockIdx.y;
    const float* X = (z == 0) ? Xk : (z == 1) ? Xv : Xq;
    float* D = g_xr + (size_t)z * BNUM * SEQ * EMBD;
    const int i = blockIdx.x * 256 + threadIdx.x;   // float4 index, 1M per tensor
    float4 v = *(const float4*)(X + (size_t)i * 4);
    v.x = to_tf32(v.x); v.y = to_tf32(v.y); v.z = to_tf32(v.z); v.w = to_tf32(v.w);
    *(float4*)(D + (size_t)i * 4) = v;
}

// ---------------------------------------------------------------------------
// Weight transposes (once per launch), baking in tf32 rounding.
// ---------------------------------------------------------------------------
__global__ __launch_bounds__(256) void transpose_w(const float* __restrict__ Wk,
                                                   const float* __restrict__ Wv,
                                                   const float* __restrict__ Wq)
{
    __shared__ float sm[32][65];
    const int z = blockIdx.z;
    const float* W = (z == 0) ? Wk : (z == 1) ? Wv : Wq;
    float* WT = g_wT + (size_t)z * EMBD * EMBD;
    const int h = blockIdx.x;
    const int k0 = blockIdx.y * 32;
    const int tid = threadIdx.x;

    for (int idx = tid; idx < 32 * 64; idx += 256) {
        const int r = idx >> 6, d = idx & 63;
        sm[r][d] = to_tf32(W[((size_t)h * EMBD + (k0 + r)) * HD + d]);
    }
    __syncthreads();
    for (int idx = tid; idx < 64 * 32; idx += 256) {
        const int dd = idx >> 5, kk = idx & 31;
        WT[(size_t)(h * HD + dd) * EMBD + k0 + kk] = sm[kk][dd];
    }
}

__global__ __launch_bounds__(256) void transpose_wo(const float* __restrict__ Wo)
{
    __shared__ float sm[32][33];
    const int n0 = blockIdx.x * 32;
    const int k0 = blockIdx.y * 32;
    const int tid = threadIdx.x;

    for (int idx = tid; idx < 1024; idx += 256) {
        const int r = idx >> 5, c = idx & 31;
        sm[r][c] = to_tf32(Wo[(size_t)(k0 + r) * EMBD + n0 + c]);
    }
    __syncthreads();
    for (int idx = tid; idx < 1024; idx += 256) {
        const int rr = idx >> 5, cc = idx & 31;
        g_woT[(size_t)(n0 + rr) * EMBD + k0 + cc] = sm[cc][rr];
    }
}

// ---------------------------------------------------------------------------
// Tensor-core flash attention (unchanged from R4 except ctx tf32 rounding).
// ---------------------------------------------------------------------------
#define KP 68
#define ATTN_SMEM ((2 * 64 * KP + 8 * 16 * KP) * (int)sizeof(float))

__global__ __launch_bounds__(256, 1) void attn_tc()
{
    extern __shared__ float smf[];
    float* Ks = smf;               // [64 keys][KP d]
    float* Vt = Ks + 64 * KP;      // [64 d][KP keys]
    float* Ps = Vt + 64 * KP;      // [8 warps][16 q][KP keys]

    const int bh = blockIdx.x;
    const int qt = 7 - blockIdx.y;        // heavy tiles first
    const int q0 = qt * 128;
    const int tid = threadIdx.x, lane = tid & 31, warp = tid >> 5;
    const int g = lane >> 2, tg = lane & 3;
    const int wq = q0 + warp * 16;

    const float* Qg = g_q  + (size_t)bh * SEQ * HD;
    const float* Kg = g_k  + (size_t)bh * SEQ * HD;
    const float* Vg = g_vT + (size_t)bh * HD * SEQ;
    float* Pw = Ps + warp * 16 * KP;

    uint32_t aq[8][4];
    #pragma unroll
    for (int kk = 0; kk < 8; kk++) {
        aq[kk][0] = __float_as_uint(Qg[(size_t)(wq + g)     * HD + kk * 8 + tg]);
        aq[kk][1] = __float_as_uint(Qg[(size_t)(wq + g + 8) * HD + kk * 8 + tg]);
        aq[kk][2] = __float_as_uint(Qg[(size_t)(wq + g)     * HD + kk * 8 + tg + 4]);
        aq[kk][3] = __float_as_uint(Qg[(size_t)(wq + g + 8) * HD + kk * 8 + tg + 4]);
    }

    float o[8][4] = {};
    float m_r[2] = { NEG_INF, NEG_INF };
    float l_r[2] = { 0.0f, 0.0f };

    const int ktend = 2 * qt + 2;
    for (int kt = 0; kt < ktend; kt++) {
        const int k0 = kt * 64;

        #pragma unroll
        for (int i = 0; i < 4; i++) {
            const int idx = i * 256 + tid;
            const int r = idx >> 4, c4 = (idx & 15) * 4;
            *(float4*)&Ks[r * KP + c4] = *(const float4*)(Kg + (size_t)(k0 + r) * HD + c4);
            *(float4*)&Vt[r * KP + c4] = *(const float4*)(Vg + (size_t)r * SEQ + k0 + c4);
        }
        __syncthreads();

        float cs[8][4] = {};
        #pragma unroll
        for (int kk = 0; kk < 8; kk++) {
            uint32_t bf[8][2];
            #pragma unroll
            for (int ni = 0; ni < 8; ni++) {
                bf[ni][0] = __float_as_uint(Ks[(ni * 8 + g) * KP + kk * 8 + tg]);
                bf[ni][1] = __float_as_uint(Ks[(ni * 8 + g) * KP + kk * 8 + tg + 4]);
            }
            #pragma unroll
            for (int ni = 0; ni < 8; ni++)
                mma_m16n8k8(cs[ni], aq[kk], bf[ni][0], bf[ni][1]);
        }

        const bool msk = (kt >= 2 * qt);
        #pragma unroll
        for (int ni = 0; ni < 8; ni++) {
            #pragma unroll
            for (int e = 0; e < 4; e++) {
                float s = cs[ni][e] * ATT_SCALE;
                if (msk) {
                    const int q = wq + g + ((e >> 1) << 3);
                    const int k = k0 + ni * 8 + tg * 2 + (e & 1);
                    if (k > q) s = NEG_INF;
                }
                cs[ni][e] = s;
            }
        }

        #pragma unroll
        for (int hh = 0; hh < 2; hh++) {
            float mx = NEG_INF;
            #pragma unroll
            for (int ni = 0; ni < 8; ni++)
                mx = fmaxf(mx, fmaxf(cs[ni][2 * hh], cs[ni][2 * hh + 1]));
            mx = fmaxf(mx, __shfl_xor_sync(0xffffffff, mx, 1));
            mx = fmaxf(mx, __shfl_xor_sync(0xffffffff, mx, 2));
            const float mnew = fmaxf(m_r[hh], mx);
            const float alpha = __expf(m_r[hh] - mnew);
            float sum = 0.0f;
            #pragma unroll
            for (int ni = 0; ni < 8; ni++) {
                const float p0 = __expf(cs[ni][2 * hh]     - mnew);
                const float p1 = __expf(cs[ni][2 * hh + 1] - mnew);
                cs[ni][2 * hh] = p0; cs[ni][2 * hh + 1] = p1;
                sum += p0 + p1;
            }
            sum += __shfl_xor_sync(0xffffffff, sum, 1);
            sum += __shfl_xor_sync(0xffffffff, sum, 2);
            l_r[hh] = l_r[hh] * alpha + sum;
            m_r[hh] = mnew;
            #pragma unroll
            for (int ni = 0; ni < 8; ni++) {
                o[ni][2 * hh] *= alpha; o[ni][2 * hh + 1] *= alpha;
            }
        }

        #pragma unroll
        for (int ni = 0; ni < 8; ni++) {
            Pw[g * KP + ni * 8 + tg * 2]           = to_tf32(cs[ni][0]);
            Pw[g * KP + ni * 8 + tg * 2 + 1]       = to_tf32(cs[ni][1]);
            Pw[(g + 8) * KP + ni * 8 + tg * 2]     = to_tf32(cs[ni][2]);
            Pw[(g + 8) * KP + ni * 8 + tg * 2 + 1] = to_tf32(cs[ni][3]);
        }
        __syncwarp();

        #pragma unroll
        for (int kk = 0; kk < 8; kk++) {
            uint32_t ap[4];
            ap[0] = __float_as_uint(Pw[g * KP + kk * 8 + tg]);
            ap[1] = __float_as_uint(Pw[(g + 8) * KP + kk * 8 + tg]);
            ap[2] = __float_as_uint(Pw[g * KP + kk * 8 + tg + 4]);
            ap[3] = __float_as_uint(Pw[(g + 8) * KP + kk * 8 + tg + 4]);
            uint32_t bv[8][2];
            #pragma unroll
            for (int ni = 0; ni < 8; ni++) {
                bv[ni][0] = __float_as_uint(Vt[(ni * 8 + g) * KP + kk * 8 + tg]);
                bv[ni][1] = __float_as_uint(Vt[(ni * 8 + g) * KP + kk * 8 + tg + 4]);
            }
            #pragma unroll
            for (int ni = 0; ni < 8; ni++)
                mma_m16n8k8(o[ni], ap, bv[ni][0], bv[ni][1]);
        }
        __syncthreads();
    }

    const int b = bh >> 4;
    const int h4 = bh & 15;
    const float inv0 = 1.0f / l_r[0];
    const float inv1 = 1.0f / l_r[1];
    #pragma unroll
    for (int ni = 0; ni < 8; ni++) {
        const int d = h4 * 64 + ni * 8 + tg * 2;
        const int r0 = wq + g, r1 = wq + g + 8;
        *(float2*)&g_ctx[(size_t)(b * SEQ + r0) * EMBD + d] =
            make_float2(to_tf32(o[ni][0] * inv0), to_tf32(o[ni][1] * inv0));
        *(float2*)&g_ctx[(size_t)(b * SEQ + r1) * EMBD + d] =
            make_float2(to_tf32(o[ni][2] * inv1), to_tf32(o[ni][3] * inv1));
    }
}

// ---------------------------------------------------------------------------
extern "C" void kernel_launch(void* const* d_in, const int* in_sizes, int n_in,
                              void* d_out, int out_size)
{
    const float* Xk = (const float*)d_in[0];
    const float* Xv = (const float*)d_in[1];
    const float* Xq = (const float*)d_in[2];
    const float* Wk = (const float*)d_in[3];
    const float* Wv = (const float*)d_in[4];
    const float* Wq = (const float*)d_in[5];
    const float* Wo = (const float*)d_in[6];
    const float* bo = (const float*)d_in[7];
    float* out = (float*)d_out;

    cudaFuncSetAttribute(proj_tc, cudaFuncAttributeMaxDynamicSharedMemorySize, GEMM_SMEM);
    cudaFuncSetAttribute(outproj_tc, cudaFuncAttributeMaxDynamicSharedMemorySize, GEMM_SMEM);
    cudaFuncSetAttribute(attn_tc, cudaFuncAttributeMaxDynamicSharedMemorySize, ATTN_SMEM);

    // 0) pre-round inputs + transpose weights to [N,K] K-major (tf32)
    round_inputs<<<dim3(4096, 3), 256>>>(Xk, Xv, Xq);
    transpose_w<<<dim3(NH, 32, 3), 256>>>(Wk, Wv, Wq);
    transpose_wo<<<dim3(32, 32), 256>>>(Wo);
    // 1) QKV projections (cp.async + ldmatrix + mma tf32)
    proj_tc<<<dim3(32, 8, 3), 256, GEMM_SMEM>>>();
    // 2) causal flash attention on tensor cores
    attn_tc<<<dim3(BH, 8), 256, ATTN_SMEM>>>();
    // 3) output projection + bias + relu
    outproj_tc<<<dim3(32, 8), 256, GEMM_SMEM>>>(bo, out);
}

// round 6
// speedup vs baseline: 3.8331x; 1.1066x over previous
#include <cuda_runtime.h>
#include <cstdint>

// Problem constants
#define BNUM 4
#define SEQ  1024
#define EMBD 1024
#define NH   16
#define HD   64
#define BH   (BNUM * NH)
#define ATT_SCALE (1.0f / 32.0f)   // 1/sqrt(1024), applied to (logits+mask)
#define NEG_INF __int_as_float(0xff800000)

// Scratch (allocation-free contract: __device__ globals)
__device__ float g_q[BH * SEQ * HD];          // [bh][s][d], tf32-rounded
__device__ float g_k[BH * SEQ * HD];          // [bh][s][d], tf32-rounded
__device__ float g_vT[BH * HD * SEQ];         // [bh][d][s], tf32-rounded
__device__ float g_ctx[BNUM * SEQ * EMBD];    // tf32-rounded (attn epilogue)
__device__ float g_xr[3 * BNUM * SEQ * EMBD]; // tf32-rounded inputs k/v/q
// Transposed (B = [N,K] K-major) weights, pre-rounded to tf32
__device__ float g_wT[3 * EMBD * EMBD];       // k/v/q
__device__ float g_woT[EMBD * EMBD];

__device__ __forceinline__ float to_tf32(float x) {
    float y; asm("cvt.rna.tf32.f32 %0, %1;" : "=f"(y) : "f"(x)); return y;
}
__device__ __forceinline__ uint32_t smem_u32(const void* p) {
    uint32_t a;
    asm("{ .reg .u64 t; cvta.to.shared.u64 t, %1; cvt.u32.u64 %0, t; }"
        : "=r"(a) : "l"(p));
    return a;
}

__device__ __forceinline__ void mma_m16n8k8(float (&d)[4], const uint32_t (&a)[4],
                                            const uint32_t b0, const uint32_t b1) {
    asm volatile(
        "mma.sync.aligned.m16n8k8.row.col.f32.tf32.tf32.f32 "
        "{%0,%1,%2,%3}, {%4,%5,%6,%7}, {%8,%9}, {%0,%1,%2,%3};"
        : "+f"(d[0]), "+f"(d[1]), "+f"(d[2]), "+f"(d[3])
        : "r"(a[0]), "r"(a[1]), "r"(a[2]), "r"(a[3]), "r"(b0), "r"(b1));
}

#define LDMX4(r, addr) \
    asm volatile("ldmatrix.sync.aligned.m8n8.x4.shared.b16 {%0,%1,%2,%3}, [%4];" \
        : "=r"((r)[0]), "=r"((r)[1]), "=r"((r)[2]), "=r"((r)[3]) : "r"(addr))

#define CP16(dst, src) \
    asm volatile("cp.async.cg.shared.global [%0], [%1], 16;" :: "r"(dst), "l"(src))
#define CP_COMMIT() asm volatile("cp.async.commit_group;" ::: "memory")
template<int N> __device__ __forceinline__ void cp_wait() {
    asm volatile("cp.async.wait_group %0;" :: "n"(N) : "memory");
}

// ---------------------------------------------------------------------------
// tf32 tensor-core GEMM: C[128x128] = A[M,K] @ Bt[N,K]^T, K=1024, BK=32.
// 3-stage cp.async pipeline; ldmatrix tf32 fragments; 8 warps, warp tile 64x32.
// __launch_bounds__(256,2): cap regs at 128 so 2 CTAs co-reside per SM and
// cross-CTA scheduling hides the per-chunk sync bubbles.
// ---------------------------------------------------------------------------
#define TILE_BYTES 16384                // 128 rows * 8 chunks * 16B
#define GEMM_SMEM  (3 * 2 * TILE_BYTES) // 3 stages x (A,B) = 96KB (2 CTAs fit 228KB)

__device__ __forceinline__ void gemm_tf32(const float* __restrict__ A,
                                          const float* __restrict__ Bt,
                                          char* sm, float (&c)[4][4][4])
{
    const int tid  = threadIdx.x;
    const int lane = tid & 31;
    const int warp = tid >> 5;
    const int m0   = blockIdx.x * 128;
    const int n0   = blockIdx.y * 128;
    const uint32_t sb = smem_u32(sm);

    auto issue = [&](int stage, int k0) {
        const uint32_t sa  = sb + stage * 2 * TILE_BYTES;
        const uint32_t sbb = sa + TILE_BYTES;
        #pragma unroll
        for (int i = 0; i < 4; i++) {
            const int idx = i * 256 + tid;
            const int row = idx >> 3, ch = idx & 7;
            const uint32_t off = (uint32_t)((row << 3) + (ch ^ (row & 7))) << 4;
            CP16(sa  + off, A  + (size_t)(m0 + row) * EMBD + k0 + ch * 4);
            CP16(sbb + off, Bt + (size_t)(n0 + row) * EMBD + k0 + ch * 4);
        }
        CP_COMMIT();
    };

    issue(0, 0);
    issue(1, 32);

    const int l7   = lane & 7;
    const int wm   = (warp & 1) * 64;
    const int wn   = (warp >> 1) * 32;
    const int aRow = wm + l7 + ((lane >> 3) & 1) * 8;  // + mi*16
    const int aChO = lane >> 4;                        // 0/1 (k lo/hi half)
    const int bRow = wn + l7 + (lane >> 4) * 8;        // + pair*16
    const int bChO = (lane >> 3) & 1;

    for (int ch = 0; ch < 32; ch++) {
        const int st = ch % 3;
        if (ch < 30) cp_wait<1>(); else cp_wait<0>();
        __syncthreads();
        const uint32_t sa  = sb + st * 2 * TILE_BYTES;
        const uint32_t sbb = sa + TILE_BYTES;

        #pragma unroll
        for (int ks = 0; ks < 4; ks++) {
            uint32_t af[4][4], bq[2][4];
            #pragma unroll
            for (int mi = 0; mi < 4; mi++) {
                const int row = aRow + mi * 16;
                const uint32_t addr =
                    sa + ((uint32_t)((row << 3) + ((ks * 2 + aChO) ^ (row & 7))) << 4);
                LDMX4(af[mi], addr);
            }
            #pragma unroll
            for (int p = 0; p < 2; p++) {
                const int row = bRow + p * 16;
                const uint32_t addr =
                    sbb + ((uint32_t)((row << 3) + ((ks * 2 + bChO) ^ (row & 7))) << 4);
                LDMX4(bq[p], addr);
            }
            #pragma unroll
            for (int mi = 0; mi < 4; mi++)
                #pragma unroll
                for (int ni = 0; ni < 4; ni++)
                    mma_m16n8k8(c[mi][ni], af[mi],
                                bq[ni >> 1][(ni & 1) * 2],
                                bq[ni >> 1][(ni & 1) * 2 + 1]);
        }

        if (ch + 2 < 32) issue((ch + 2) % 3, (ch + 2) * 32);
    }
}

// Projection: outputs tf32-rounded Q/K (as [bh][s][d]) and V transposed [bh][d][s]
__global__ __launch_bounds__(256, 2) void proj_tc()
{
    extern __shared__ char smc[];
    const int z = blockIdx.z;
    const float* A  = g_xr + (size_t)z * BNUM * SEQ * EMBD;
    const float* Bt = g_wT + (size_t)z * EMBD * EMBD;

    float c[4][4][4] = {};
    gemm_tf32(A, Bt, smc, c);

    const int tid = threadIdx.x;
    const int lane = tid & 31, warp = tid >> 5;
    const int wm = (warp & 1) * 64, wn = (warp >> 1) * 32;
    const int g = lane >> 2, tg = lane & 3;
    const int m0 = blockIdx.x * 128, n0 = blockIdx.y * 128;

    if (z == 1) {
        // V -> g_vT [bh][d][s]
        #pragma unroll
        for (int mi = 0; mi < 4; mi++) {
            #pragma unroll
            for (int ni = 0; ni < 4; ni++) {
                const int n = n0 + wn + ni * 8 + tg * 2;
                const int h = n >> 6, d = n & 63;
                #pragma unroll
                for (int half = 0; half < 2; half++) {
                    const int m = m0 + wm + mi * 16 + g + half * 8;
                    const int b = m >> 10, s = m & 1023;
                    const size_t base = (size_t)(b * NH + h) * HD;
                    g_vT[(base + d)     * SEQ + s] = to_tf32(c[mi][ni][half * 2]);
                    g_vT[(base + d + 1) * SEQ + s] = to_tf32(c[mi][ni][half * 2 + 1]);
                }
            }
        }
    } else {
        float* Out = (z == 0) ? g_k : g_q;
        #pragma unroll
        for (int mi = 0; mi < 4; mi++) {
            #pragma unroll
            for (int ni = 0; ni < 4; ni++) {
                const int n = n0 + wn + ni * 8 + tg * 2;
                const int h = n >> 6, d = n & 63;
                #pragma unroll
                for (int half = 0; half < 2; half++) {
                    const int m = m0 + wm + mi * 16 + g + half * 8;
                    const int b = m >> 10, s = m & 1023;
                    float2 v = make_float2(to_tf32(c[mi][ni][half * 2]),
                                           to_tf32(c[mi][ni][half * 2 + 1]));
                    *(float2*)&Out[((size_t)(b * NH + h) * SEQ + s) * HD + d] = v;
                }
            }
        }
    }
}

// Output projection: A = g_ctx (tf32-rounded), Bt = g_woT, bias + relu
__global__ __launch_bounds__(256, 2) void outproj_tc(const float* __restrict__ bo,
                                                     float* __restrict__ out)
{
    extern __shared__ char smc[];
    float c[4][4][4] = {};
    gemm_tf32(g_ctx, g_woT, smc, c);

    const int tid = threadIdx.x;
    const int lane = tid & 31, warp = tid >> 5;
    const int wm = (warp & 1) * 64, wn = (warp >> 1) * 32;
    const int g = lane >> 2, tg = lane & 3;
    const int m0 = blockIdx.x * 128, n0 = blockIdx.y * 128;

    #pragma unroll
    for (int mi = 0; mi < 4; mi++) {
        #pragma unroll
        for (int ni = 0; ni < 4; ni++) {
            const int n = n0 + wn + ni * 8 + tg * 2;
            const float b0 = bo[n], b1 = bo[n + 1];
            #pragma unroll
            for (int half = 0; half < 2; half++) {
                const int m = m0 + wm + mi * 16 + g + half * 8;
                float2 v = make_float2(fmaxf(c[mi][ni][half * 2]     + b0, 0.0f),
                                       fmaxf(c[mi][ni][half * 2 + 1] + b1, 0.0f));
                *(float2*)&out[(size_t)m * EMBD + n] = v;
            }
        }
    }
}

// ---------------------------------------------------------------------------
// Input pre-rounding to tf32 (cp.async path cannot convert in-flight)
// ---------------------------------------------------------------------------
__global__ __launch_bounds__(256) void round_inputs(const float* __restrict__ Xk,
                                                    const float* __restrict__ Xv,
                                                    const float* __restrict__ Xq)
{
    const int z = blockIdx.y;
    const float* X = (z == 0) ? Xk : (z == 1) ? Xv : Xq;
    float* D = g_xr + (size_t)z * BNUM * SEQ * EMBD;
    const int i = blockIdx.x * 256 + threadIdx.x;   // float4 index, 1M per tensor
    float4 v = *(const float4*)(X + (size_t)i * 4);
    v.x = to_tf32(v.x); v.y = to_tf32(v.y); v.z = to_tf32(v.z); v.w = to_tf32(v.w);
    *(float4*)(D + (size_t)i * 4) = v;
}

// ---------------------------------------------------------------------------
// Weight transposes (once per launch), baking in tf32 rounding.
// ---------------------------------------------------------------------------
__global__ __launch_bounds__(256) void transpose_w(const float* __restrict__ Wk,
                                                   const float* __restrict__ Wv,
                                                   const float* __restrict__ Wq)
{
    __shared__ float sm[32][65];
    const int z = blockIdx.z;
    const float* W = (z == 0) ? Wk : (z == 1) ? Wv : Wq;
    float* WT = g_wT + (size_t)z * EMBD * EMBD;
    const int h = blockIdx.x;
    const int k0 = blockIdx.y * 32;
    const int tid = threadIdx.x;

    for (int idx = tid; idx < 32 * 64; idx += 256) {
        const int r = idx >> 6, d = idx & 63;
        sm[r][d] = to_tf32(W[((size_t)h * EMBD + (k0 + r)) * HD + d]);
    }
    __syncthreads();
    for (int idx = tid; idx < 64 * 32; idx += 256) {
        const int dd = idx >> 5, kk = idx & 31;
        WT[(size_t)(h * HD + dd) * EMBD + k0 + kk] = sm[kk][dd];
    }
}

__global__ __launch_bounds__(256) void transpose_wo(const float* __restrict__ Wo)
{
    __shared__ float sm[32][33];
    const int n0 = blockIdx.x * 32;
    const int k0 = blockIdx.y * 32;
    const int tid = threadIdx.x;

    for (int idx = tid; idx < 1024; idx += 256) {
        const int r = idx >> 5, c = idx & 31;
        sm[r][c] = to_tf32(Wo[(size_t)(k0 + r) * EMBD + n0 + c]);
    }
    __syncthreads();
    for (int idx = tid; idx < 1024; idx += 256) {
        const int rr = idx >> 5, cc = idx & 31;
        g_woT[(size_t)(n0 + rr) * EMBD + k0 + cc] = sm[cc][rr];
    }
}

// ---------------------------------------------------------------------------
// Tensor-core flash attention (unchanged this round).
// ---------------------------------------------------------------------------
#define KP 68
#define ATTN_SMEM ((2 * 64 * KP + 8 * 16 * KP) * (int)sizeof(float))

__global__ __launch_bounds__(256, 1) void attn_tc()
{
    extern __shared__ float smf[];
    float* Ks = smf;               // [64 keys][KP d]
    float* Vt = Ks + 64 * KP;      // [64 d][KP keys]
    float* Ps = Vt + 64 * KP;      // [8 warps][16 q][KP keys]

    const int bh = blockIdx.x;
    const int qt = 7 - blockIdx.y;        // heavy tiles first
    const int q0 = qt * 128;
    const int tid = threadIdx.x, lane = tid & 31, warp = tid >> 5;
    const int g = lane >> 2, tg = lane & 3;
    const int wq = q0 + warp * 16;

    const float* Qg = g_q  + (size_t)bh * SEQ * HD;
    const float* Kg = g_k  + (size_t)bh * SEQ * HD;
    const float* Vg = g_vT + (size_t)bh * HD * SEQ;
    float* Pw = Ps + warp * 16 * KP;

    uint32_t aq[8][4];
    #pragma unroll
    for (int kk = 0; kk < 8; kk++) {
        aq[kk][0] = __float_as_uint(Qg[(size_t)(wq + g)     * HD + kk * 8 + tg]);
        aq[kk][1] = __float_as_uint(Qg[(size_t)(wq + g + 8) * HD + kk * 8 + tg]);
        aq[kk][2] = __float_as_uint(Qg[(size_t)(wq + g)     * HD + kk * 8 + tg + 4]);
        aq[kk][3] = __float_as_uint(Qg[(size_t)(wq + g + 8) * HD + kk * 8 + tg + 4]);
    }

    float o[8][4] = {};
    float m_r[2] = { NEG_INF, NEG_INF };
    float l_r[2] = { 0.0f, 0.0f };

    const int ktend = 2 * qt + 2;
    for (int kt = 0; kt < ktend; kt++) {
        const int k0 = kt * 64;

        #pragma unroll
        for (int i = 0; i < 4; i++) {
            const int idx = i * 256 + tid;
            const int r = idx >> 4, c4 = (idx & 15) * 4;
            *(float4*)&Ks[r * KP + c4] = *(const float4*)(Kg + (size_t)(k0 + r) * HD + c4);
            *(float4*)&Vt[r * KP + c4] = *(const float4*)(Vg + (size_t)r * SEQ + k0 + c4);
        }
        __syncthreads();

        float cs[8][4] = {};
        #pragma unroll
        for (int kk = 0; kk < 8; kk++) {
            uint32_t bf[8][2];
            #pragma unroll
            for (int ni = 0; ni < 8; ni++) {
                bf[ni][0] = __float_as_uint(Ks[(ni * 8 + g) * KP + kk * 8 + tg]);
                bf[ni][1] = __float_as_uint(Ks[(ni * 8 + g) * KP + kk * 8 + tg + 4]);
            }
            #pragma unroll
            for (int ni = 0; ni < 8; ni++)
                mma_m16n8k8(cs[ni], aq[kk], bf[ni][0], bf[ni][1]);
        }

        const bool msk = (kt >= 2 * qt);
        #pragma unroll
        for (int ni = 0; ni < 8; ni++) {
            #pragma unroll
            for (int e = 0; e < 4; e++) {
                float s = cs[ni][e] * ATT_SCALE;
                if (msk) {
                    const int q = wq + g + ((e >> 1) << 3);
                    const int k = k0 + ni * 8 + tg * 2 + (e & 1);
                    if (k > q) s = NEG_INF;
                }
                cs[ni][e] = s;
            }
        }

        #pragma unroll
        for (int hh = 0; hh < 2; hh++) {
            float mx = NEG_INF;
            #pragma unroll
            for (int ni = 0; ni < 8; ni++)
                mx = fmaxf(mx, fmaxf(cs[ni][2 * hh], cs[ni][2 * hh + 1]));
            mx = fmaxf(mx, __shfl_xor_sync(0xffffffff, mx, 1));
            mx = fmaxf(mx, __shfl_xor_sync(0xffffffff, mx, 2));
            const float mnew = fmaxf(m_r[hh], mx);
            const float alpha = __expf(m_r[hh] - mnew);
            float sum = 0.0f;
            #pragma unroll
            for (int ni = 0; ni < 8; ni++) {
                const float p0 = __expf(cs[ni][2 * hh]     - mnew);
                const float p1 = __expf(cs[ni][2 * hh + 1] - mnew);
                cs[ni][2 * hh] = p0; cs[ni][2 * hh + 1] = p1;
                sum += p0 + p1;
            }
            sum += __shfl_xor_sync(0xffffffff, sum, 1);
            sum += __shfl_xor_sync(0xffffffff, sum, 2);
            l_r[hh] = l_r[hh] * alpha + sum;
            m_r[hh] = mnew;
            #pragma unroll
            for (int ni = 0; ni < 8; ni++) {
                o[ni][2 * hh] *= alpha; o[ni][2 * hh + 1] *= alpha;
            }
        }

        #pragma unroll
        for (int ni = 0; ni < 8; ni++) {
            Pw[g * KP + ni * 8 + tg * 2]           = to_tf32(cs[ni][0]);
            Pw[g * KP + ni * 8 + tg * 2 + 1]       = to_tf32(cs[ni][1]);
            Pw[(g + 8) * KP + ni * 8 + tg * 2]     = to_tf32(cs[ni][2]);
            Pw[(g + 8) * KP + ni * 8 + tg * 2 + 1] = to_tf32(cs[ni][3]);
        }
        __syncwarp();

        #pragma unroll
        for (int kk = 0; kk < 8; kk++) {
            uint32_t ap[4];
            ap[0] = __float_as_uint(Pw[g * KP + kk * 8 + tg]);
            ap[1] = __float_as_uint(Pw[(g + 8) * KP + kk * 8 + tg]);
            ap[2] = __float_as_uint(Pw[g * KP + kk * 8 + tg + 4]);
            ap[3] = __float_as_uint(Pw[(g + 8) * KP + kk * 8 + tg + 4]);
            uint32_t bv[8][2];
            #pragma unroll
            for (int ni = 0; ni < 8; ni++) {
                bv[ni][0] = __float_as_uint(Vt[(ni * 8 + g) * KP + kk * 8 + tg]);
                bv[ni][1] = __float_as_uint(Vt[(ni * 8 + g) * KP + kk * 8 + tg + 4]);
            }
            #pragma unroll
            for (int ni = 0; ni < 8; ni++)
                mma_m16n8k8(o[ni], ap, bv[ni][0], bv[ni][1]);
        }
        __syncthreads();
    }

    const int b = bh >> 4;
    const int h4 = bh & 15;
    const float inv0 = 1.0f / l_r[0];
    const float inv1 = 1.0f / l_r[1];
    #pragma unroll
    for (int ni = 0; ni < 8; ni++) {
        const int d = h4 * 64 + ni * 8 + tg * 2;
        const int r0 = wq + g, r1 = wq + g + 8;
        *(float2*)&g_ctx[(size_t)(b * SEQ + r0) * EMBD + d] =
            make_float2(to_tf32(o[ni][0] * inv0), to_tf32(o[ni][1] * inv0));
        *(float2*)&g_ctx[(size_t)(b * SEQ + r1) * EMBD + d] =
            make_float2(to_tf32(o[ni][2] * inv1), to_tf32(o[ni][3] * inv1));
    }
}

// ---------------------------------------------------------------------------
extern "C" void kernel_launch(void* const* d_in, const int* in_sizes, int n_in,
                              void* d_out, int out_size)
{
    const float* Xk = (const float*)d_in[0];
    const float* Xv = (const float*)d_in[1];
    const float* Xq = (const float*)d_in[2];
    const float* Wk = (const float*)d_in[3];
    const float* Wv = (const float*)d_in[4];
    const float* Wq = (const float*)d_in[5];
    const float* Wo = (const float*)d_in[6];
    const float* bo = (const float*)d_in[7];
    float* out = (float*)d_out;

    cudaFuncSetAttribute(proj_tc, cudaFuncAttributeMaxDynamicSharedMemorySize, GEMM_SMEM);
    cudaFuncSetAttribute(outproj_tc, cudaFuncAttributeMaxDynamicSharedMemorySize, GEMM_SMEM);
    cudaFuncSetAttribute(attn_tc, cudaFuncAttributeMaxDynamicSharedMemorySize, ATTN_SMEM);

    // 0) pre-round inputs + transpose weights to [N,K] K-major (tf32)
    round_inputs<<<dim3(4096, 3), 256>>>(Xk, Xv, Xq);
    transpose_w<<<dim3(NH, 32, 3), 256>>>(Wk, Wv, Wq);
    transpose_wo<<<dim3(32, 32), 256>>>(Wo);
    // 1) QKV projections (cp.async + ldmatrix + mma tf32, 2 CTAs/SM)
    proj_tc<<<dim3(32, 8, 3), 256, GEMM_SMEM>>>();
    // 2) causal flash attention on tensor cores
    attn_tc<<<dim3(BH, 8), 256, ATTN_SMEM>>>();
    // 3) output projection + bias + relu (2 CTAs/SM)
    outproj_tc<<<dim3(32, 8), 256, GEMM_SMEM>>>(bo, out);
}

// round 7
// speedup vs baseline: 4.0738x; 1.0628x over previous
#include <cuda_runtime.h>
#include <cstdint>

// Problem constants
#define BNUM 4
#define SEQ  1024
#define EMBD 1024
#define NH   16
#define HD   64
#define BH   (BNUM * NH)
#define ATT_SCALE (1.0f / 32.0f)   // 1/sqrt(1024), applied to (logits+mask)
#define NEG_INF __int_as_float(0xff800000)

// Scratch (allocation-free contract: __device__ globals)
__device__ float g_q[BH * SEQ * HD];          // [bh][s][d], tf32-rounded
__device__ float g_k[BH * SEQ * HD];          // [bh][s][d], tf32-rounded
__device__ float g_vT[BH * HD * SEQ];         // [bh][d][s], tf32-rounded
__device__ float g_ctx[BNUM * SEQ * EMBD];    // tf32-rounded (attn epilogue)
__device__ float g_xr[3 * BNUM * SEQ * EMBD]; // tf32-rounded inputs k/v/q
// Transposed (B = [N,K] K-major) weights, pre-rounded to tf32
__device__ float g_wT[3 * EMBD * EMBD];       // k/v/q
__device__ float g_woT[EMBD * EMBD];

__device__ __forceinline__ float to_tf32(float x) {
    float y; asm("cvt.rna.tf32.f32 %0, %1;" : "=f"(y) : "f"(x)); return y;
}
__device__ __forceinline__ uint32_t smem_u32(const void* p) {
    uint32_t a;
    asm("{ .reg .u64 t; cvta.to.shared.u64 t, %1; cvt.u32.u64 %0, t; }"
        : "=r"(a) : "l"(p));
    return a;
}

__device__ __forceinline__ void mma_m16n8k8(float (&d)[4], const uint32_t (&a)[4],
                                            const uint32_t b0, const uint32_t b1) {
    asm volatile(
        "mma.sync.aligned.m16n8k8.row.col.f32.tf32.tf32.f32 "
        "{%0,%1,%2,%3}, {%4,%5,%6,%7}, {%8,%9}, {%0,%1,%2,%3};"
        : "+f"(d[0]), "+f"(d[1]), "+f"(d[2]), "+f"(d[3])
        : "r"(a[0]), "r"(a[1]), "r"(a[2]), "r"(a[3]), "r"(b0), "r"(b1));
}

#define LDMX4(r, addr) \
    asm volatile("ldmatrix.sync.aligned.m8n8.x4.shared.b16 {%0,%1,%2,%3}, [%4];" \
        : "=r"((r)[0]), "=r"((r)[1]), "=r"((r)[2]), "=r"((r)[3]) : "r"(addr))

#define CP16(dst, src) \
    asm volatile("cp.async.cg.shared.global [%0], [%1], 16;" :: "r"(dst), "l"(src))
#define CP_COMMIT() asm volatile("cp.async.commit_group;" ::: "memory")
template<int N> __device__ __forceinline__ void cp_wait() {
    asm volatile("cp.async.wait_group %0;" :: "n"(N) : "memory");
}

// ---------------------------------------------------------------------------
// tf32 tensor-core GEMM: C[128x128] = A[M,K] @ Bt[N,K]^T, K=1024, BK=32.
// 3-stage cp.async pipeline (issue hoisted to right after the barrier so the
// prefetch overlaps the whole chunk's MMAs); ldmatrix tf32 fragments.
// ---------------------------------------------------------------------------
#define TILE_BYTES 16384                // 128 rows * 8 chunks * 16B
#define GEMM_SMEM  (3 * 2 * TILE_BYTES) // 3 stages x (A,B) = 96KB

__device__ __forceinline__ void gemm_tf32(const float* __restrict__ A,
                                          const float* __restrict__ Bt,
                                          char* sm, float (&c)[4][4][4])
{
    const int tid  = threadIdx.x;
    const int lane = tid & 31;
    const int warp = tid >> 5;
    const int m0   = blockIdx.x * 128;
    const int n0   = blockIdx.y * 128;
    const uint32_t sb = smem_u32(sm);

    auto issue = [&](int stage, int k0) {
        const uint32_t sa  = sb + stage * 2 * TILE_BYTES;
        const uint32_t sbb = sa + TILE_BYTES;
        #pragma unroll
        for (int i = 0; i < 4; i++) {
            const int idx = i * 256 + tid;
            const int row = idx >> 3, ch = idx & 7;
            const uint32_t off = (uint32_t)((row << 3) + (ch ^ (row & 7))) << 4;
            CP16(sa  + off, A  + (size_t)(m0 + row) * EMBD + k0 + ch * 4);
            CP16(sbb + off, Bt + (size_t)(n0 + row) * EMBD + k0 + ch * 4);
        }
        CP_COMMIT();
    };

    issue(0, 0);
    issue(1, 32);

    const int l7   = lane & 7;
    const int wm   = (warp & 1) * 64;
    const int wn   = (warp >> 1) * 32;
    const int aRow = wm + l7 + ((lane >> 3) & 1) * 8;  // + mi*16
    const int aChO = lane >> 4;                        // 0/1 (k lo/hi half)
    const int bRow = wn + l7 + (lane >> 4) * 8;        // + pair*16
    const int bChO = (lane >> 3) & 1;

    for (int ch = 0; ch < 32; ch++) {
        const int st = ch % 3;
        if (ch < 30) cp_wait<1>(); else cp_wait<0>();
        __syncthreads();
        // stage (ch+2)%3 was last read in chunk ch-1; barrier proves it's free.
        if (ch + 2 < 32) issue((ch + 2) % 3, (ch + 2) * 32);

        const uint32_t sa  = sb + st * 2 * TILE_BYTES;
        const uint32_t sbb = sa + TILE_BYTES;

        #pragma unroll
        for (int ks = 0; ks < 4; ks++) {
            uint32_t af[4][4], bq[2][4];
            #pragma unroll
            for (int mi = 0; mi < 4; mi++) {
                const int row = aRow + mi * 16;
                const uint32_t addr =
                    sa + ((uint32_t)((row << 3) + ((ks * 2 + aChO) ^ (row & 7))) << 4);
                LDMX4(af[mi], addr);
            }
            #pragma unroll
            for (int p = 0; p < 2; p++) {
                const int row = bRow + p * 16;
                const uint32_t addr =
                    sbb + ((uint32_t)((row << 3) + ((ks * 2 + bChO) ^ (row & 7))) << 4);
                LDMX4(bq[p], addr);
            }
            #pragma unroll
            for (int mi = 0; mi < 4; mi++)
                #pragma unroll
                for (int ni = 0; ni < 4; ni++)
                    mma_m16n8k8(c[mi][ni], af[mi],
                                bq[ni >> 1][(ni & 1) * 2],
                                bq[ni >> 1][(ni & 1) * 2 + 1]);
        }
    }
}

// Projection: outputs tf32-rounded Q/K (as [bh][s][d]) and V transposed [bh][d][s]
__global__ __launch_bounds__(256, 2) void proj_tc()
{
    extern __shared__ char smc[];
    const int z = blockIdx.z;
    const float* A  = g_xr + (size_t)z * BNUM * SEQ * EMBD;
    const float* Bt = g_wT + (size_t)z * EMBD * EMBD;

    float c[4][4][4] = {};
    gemm_tf32(A, Bt, smc, c);

    const int tid = threadIdx.x;
    const int lane = tid & 31, warp = tid >> 5;
    const int wm = (warp & 1) * 64, wn = (warp >> 1) * 32;
    const int g = lane >> 2, tg = lane & 3;
    const int m0 = blockIdx.x * 128, n0 = blockIdx.y * 128;

    if (z == 1) {
        // V -> g_vT [bh][d][s]
        #pragma unroll
        for (int mi = 0; mi < 4; mi++) {
            #pragma unroll
            for (int ni = 0; ni < 4; ni++) {
                const int n = n0 + wn + ni * 8 + tg * 2;
                const int h = n >> 6, d = n & 63;
                #pragma unroll
                for (int half = 0; half < 2; half++) {
                    const int m = m0 + wm + mi * 16 + g + half * 8;
                    const int b = m >> 10, s = m & 1023;
                    const size_t base = (size_t)(b * NH + h) * HD;
                    g_vT[(base + d)     * SEQ + s] = to_tf32(c[mi][ni][half * 2]);
                    g_vT[(base + d + 1) * SEQ + s] = to_tf32(c[mi][ni][half * 2 + 1]);
                }
            }
        }
    } else {
        float* Out = (z == 0) ? g_k : g_q;
        #pragma unroll
        for (int mi = 0; mi < 4; mi++) {
            #pragma unroll
            for (int ni = 0; ni < 4; ni++) {
                const int n = n0 + wn + ni * 8 + tg * 2;
                const int h = n >> 6, d = n & 63;
                #pragma unroll
                for (int half = 0; half < 2; half++) {
                    const int m = m0 + wm + mi * 16 + g + half * 8;
                    const int b = m >> 10, s = m & 1023;
                    float2 v = make_float2(to_tf32(c[mi][ni][half * 2]),
                                           to_tf32(c[mi][ni][half * 2 + 1]));
                    *(float2*)&Out[((size_t)(b * NH + h) * SEQ + s) * HD + d] = v;
                }
            }
        }
    }
}

// Output projection: A = g_ctx (tf32-rounded), Bt = g_woT, bias + relu
__global__ __launch_bounds__(256, 2) void outproj_tc(const float* __restrict__ bo,
                                                     float* __restrict__ out)
{
    extern __shared__ char smc[];
    float c[4][4][4] = {};
    gemm_tf32(g_ctx, g_woT, smc, c);

    const int tid = threadIdx.x;
    const int lane = tid & 31, warp = tid >> 5;
    const int wm = (warp & 1) * 64, wn = (warp >> 1) * 32;
    const int g = lane >> 2, tg = lane & 3;
    const int m0 = blockIdx.x * 128, n0 = blockIdx.y * 128;

    #pragma unroll
    for (int mi = 0; mi < 4; mi++) {
        #pragma unroll
        for (int ni = 0; ni < 4; ni++) {
            const int n = n0 + wn + ni * 8 + tg * 2;
            const float b0 = bo[n], b1 = bo[n + 1];
            #pragma unroll
            for (int half = 0; half < 2; half++) {
                const int m = m0 + wm + mi * 16 + g + half * 8;
                float2 v = make_float2(fmaxf(c[mi][ni][half * 2]     + b0, 0.0f),
                                       fmaxf(c[mi][ni][half * 2 + 1] + b1, 0.0f));
                *(float2*)&out[(size_t)m * EMBD + n] = v;
            }
        }
    }
}

// ---------------------------------------------------------------------------
// Input pre-rounding to tf32 (cp.async path cannot convert in-flight)
// ---------------------------------------------------------------------------
__global__ __launch_bounds__(256) void round_inputs(const float* __restrict__ Xk,
                                                    const float* __restrict__ Xv,
                                                    const float* __restrict__ Xq)
{
    const int z = blockIdx.y;
    const float* X = (z == 0) ? Xk : (z == 1) ? Xv : Xq;
    float* D = g_xr + (size_t)z * BNUM * SEQ * EMBD;
    const int i = blockIdx.x * 256 + threadIdx.x;   // float4 index, 1M per tensor
    float4 v = *(const float4*)(X + (size_t)i * 4);
    v.x = to_tf32(v.x); v.y = to_tf32(v.y); v.z = to_tf32(v.z); v.w = to_tf32(v.w);
    *(float4*)(D + (size_t)i * 4) = v;
}

// ---------------------------------------------------------------------------
// Weight transposes (once per launch), baking in tf32 rounding.
// ---------------------------------------------------------------------------
__global__ __launch_bounds__(256) void transpose_w(const float* __restrict__ Wk,
                                                   const float* __restrict__ Wv,
                                                   const float* __restrict__ Wq)
{
    __shared__ float sm[32][65];
    const int z = blockIdx.z;
    const float* W = (z == 0) ? Wk : (z == 1) ? Wv : Wq;
    float* WT = g_wT + (size_t)z * EMBD * EMBD;
    const int h = blockIdx.x;
    const int k0 = blockIdx.y * 32;
    const int tid = threadIdx.x;

    for (int idx = tid; idx < 32 * 64; idx += 256) {
        const int r = idx >> 6, d = idx & 63;
        sm[r][d] = to_tf32(W[((size_t)h * EMBD + (k0 + r)) * HD + d]);
    }
    __syncthreads();
    for (int idx = tid; idx < 64 * 32; idx += 256) {
        const int dd = idx >> 5, kk = idx & 31;
        WT[(size_t)(h * HD + dd) * EMBD + k0 + kk] = sm[kk][dd];
    }
}

__global__ __launch_bounds__(256) void transpose_wo(const float* __restrict__ Wo)
{
    __shared__ float sm[32][33];
    const int n0 = blockIdx.x * 32;
    const int k0 = blockIdx.y * 32;
    const int tid = threadIdx.x;

    for (int idx = tid; idx < 1024; idx += 256) {
        const int r = idx >> 5, c = idx & 31;
        sm[r][c] = to_tf32(Wo[(size_t)(k0 + r) * EMBD + n0 + c]);
    }
    __syncthreads();
    for (int idx = tid; idx < 1024; idx += 256) {
        const int rr = idx >> 5, cc = idx & 31;
        g_woT[(size_t)(n0 + rr) * EMBD + k0 + cc] = sm[cc][rr];
    }
}

// ---------------------------------------------------------------------------
// Tensor-core flash attention, v2:
// - K and V^T tiles loaded via cp.async into 16B-chunk XOR-swizzled layout,
//   double-buffered across key tiles (prefetch kt+1 during compute of kt)
// - K / V fragments via ldmatrix.x4 (same validated b16 trick as the GEMM)
// Tile = 64 rows x 16 chunks of 16B = 16KB; 2 bufs each for K and V^T.
// ---------------------------------------------------------------------------
#define KP 68
#define ATT_TILE 16384
#define ATTN_SMEM (4 * ATT_TILE + 8 * 16 * KP * (int)sizeof(float))

__device__ __forceinline__ uint32_t att_off(int row, int ch) {
    return (uint32_t)((row << 4) + ((ch & 8) | ((ch ^ row) & 7))) << 4;
}

__global__ __launch_bounds__(256, 1) void attn_tc()
{
    extern __shared__ char smc[];
    const uint32_t sb = smem_u32(smc);
    float* Ps = (float*)(smc + 4 * ATT_TILE);   // [8 warps][16 q][KP keys]

    const int bh = blockIdx.x;
    const int qt = 7 - blockIdx.y;        // heavy tiles first
    const int q0 = qt * 128;
    const int tid = threadIdx.x, lane = tid & 31, warp = tid >> 5;
    const int g = lane >> 2, tg = lane & 3;
    const int l7 = lane & 7;
    const int fRowO = l7 + (lane >> 4) * 8;      // B-fragment row offset
    const int fChO  = (lane >> 3) & 1;           // B-fragment chunk offset
    const int wq = q0 + warp * 16;

    const float* Qg = g_q  + (size_t)bh * SEQ * HD;
    const float* Kg = g_k  + (size_t)bh * SEQ * HD;
    const float* Vg = g_vT + (size_t)bh * HD * SEQ;
    float* Pw = Ps + warp * 16 * KP;

    auto issueKV = [&](int kt) {
        const int k0 = kt * 64;
        const uint32_t kb = sb + (kt & 1) * ATT_TILE;
        const uint32_t vb = sb + 2 * ATT_TILE + (kt & 1) * ATT_TILE;
        #pragma unroll
        for (int i = 0; i < 4; i++) {
            const int idx = i * 256 + tid;
            const int row = idx >> 4, ch = idx & 15;
            const uint32_t o = att_off(row, ch);
            CP16(kb + o, Kg + (size_t)(k0 + row) * HD + ch * 4);
            CP16(vb + o, Vg + (size_t)row * SEQ + k0 + ch * 4);
        }
        CP_COMMIT();
    };

    // Q fragments for the whole block (16 x 64, 8 k-steps)
    uint32_t aq[8][4];
    #pragma unroll
    for (int kk = 0; kk < 8; kk++) {
        aq[kk][0] = __float_as_uint(Qg[(size_t)(wq + g)     * HD + kk * 8 + tg]);
        aq[kk][1] = __float_as_uint(Qg[(size_t)(wq + g + 8) * HD + kk * 8 + tg]);
        aq[kk][2] = __float_as_uint(Qg[(size_t)(wq + g)     * HD + kk * 8 + tg + 4]);
        aq[kk][3] = __float_as_uint(Qg[(size_t)(wq + g + 8) * HD + kk * 8 + tg + 4]);
    }

    float o[8][4] = {};
    float m_r[2] = { NEG_INF, NEG_INF };
    float l_r[2] = { 0.0f, 0.0f };

    const int ktend = 2 * qt + 2;
    issueKV(0);

    for (int kt = 0; kt < ktend; kt++) {
        const int k0 = kt * 64;
        cp_wait<0>();
        __syncthreads();
        if (kt + 1 < ktend) issueKV(kt + 1);

        const uint32_t kb = sb + (kt & 1) * ATT_TILE;
        const uint32_t vb = sb + 2 * ATT_TILE + (kt & 1) * ATT_TILE;

        // S = Q K^T   (B fragments via ldmatrix)
        float cs[8][4] = {};
        #pragma unroll
        for (int kk = 0; kk < 8; kk++) {
            const int ch = 2 * kk + fChO;
            #pragma unroll
            for (int n16 = 0; n16 < 4; n16++) {
                uint32_t bk[4];
                LDMX4(bk, kb + att_off(n16 * 16 + fRowO, ch));
                mma_m16n8k8(cs[2 * n16],     aq[kk], bk[0], bk[1]);
                mma_m16n8k8(cs[2 * n16 + 1], aq[kk], bk[2], bk[3]);
            }
        }

        // scale + causal mask (only last two key tiles can cross the diagonal)
        const bool msk = (kt >= 2 * qt);
        #pragma unroll
        for (int ni = 0; ni < 8; ni++) {
            #pragma unroll
            for (int e = 0; e < 4; e++) {
                float s = cs[ni][e] * ATT_SCALE;
                if (msk) {
                    const int q = wq + g + ((e >> 1) << 3);
                    const int k = k0 + ni * 8 + tg * 2 + (e & 1);
                    if (k > q) s = NEG_INF;
                }
                cs[ni][e] = s;
            }
        }

        // online softmax (rows g and g+8), quad reductions
        #pragma unroll
        for (int hh = 0; hh < 2; hh++) {
            float mx = NEG_INF;
            #pragma unroll
            for (int ni = 0; ni < 8; ni++)
                mx = fmaxf(mx, fmaxf(cs[ni][2 * hh], cs[ni][2 * hh + 1]));
            mx = fmaxf(mx, __shfl_xor_sync(0xffffffff, mx, 1));
            mx = fmaxf(mx, __shfl_xor_sync(0xffffffff, mx, 2));
            const float mnew = fmaxf(m_r[hh], mx);
            const float alpha = __expf(m_r[hh] - mnew);
            float sum = 0.0f;
            #pragma unroll
            for (int ni = 0; ni < 8; ni++) {
                const float p0 = __expf(cs[ni][2 * hh]     - mnew);
                const float p1 = __expf(cs[ni][2 * hh + 1] - mnew);
                cs[ni][2 * hh] = p0; cs[ni][2 * hh + 1] = p1;
                sum += p0 + p1;
            }
            sum += __shfl_xor_sync(0xffffffff, sum, 1);
            sum += __shfl_xor_sync(0xffffffff, sum, 2);
            l_r[hh] = l_r[hh] * alpha + sum;
            m_r[hh] = mnew;
            #pragma unroll
            for (int ni = 0; ni < 8; ni++) {
                o[ni][2 * hh] *= alpha; o[ni][2 * hh + 1] *= alpha;
            }
        }

        // P -> warp-private SMEM (tf32)
        #pragma unroll
        for (int ni = 0; ni < 8; ni++) {
            Pw[g * KP + ni * 8 + tg * 2]           = to_tf32(cs[ni][0]);
            Pw[g * KP + ni * 8 + tg * 2 + 1]       = to_tf32(cs[ni][1]);
            Pw[(g + 8) * KP + ni * 8 + tg * 2]     = to_tf32(cs[ni][2]);
            Pw[(g + 8) * KP + ni * 8 + tg * 2 + 1] = to_tf32(cs[ni][3]);
        }
        __syncwarp();

        // O += P V   (B = V^T fragments via ldmatrix)
        #pragma unroll
        for (int kk = 0; kk < 8; kk++) {
            uint32_t ap[4];
            ap[0] = __float_as_uint(Pw[g * KP + kk * 8 + tg]);
            ap[1] = __float_as_uint(Pw[(g + 8) * KP + kk * 8 + tg]);
            ap[2] = __float_as_uint(Pw[g * KP + kk * 8 + tg + 4]);
            ap[3] = __float_as_uint(Pw[(g + 8) * KP + kk * 8 + tg + 4]);
            const int ch = 2 * kk + fChO;
            #pragma unroll
            for (int n16 = 0; n16 < 4; n16++) {
                uint32_t bv[4];
                LDMX4(bv, vb + att_off(n16 * 16 + fRowO, ch));
                mma_m16n8k8(o[2 * n16],     ap, bv[0], bv[1]);
                mma_m16n8k8(o[2 * n16 + 1], ap, bv[2], bv[3]);
            }
        }
    }

    // epilogue: normalize and write concat ctx (tf32-rounded for outproj)
    const int b = bh >> 4;
    const int h4 = bh & 15;
    const float inv0 = 1.0f / l_r[0];
    const float inv1 = 1.0f / l_r[1];
    #pragma unroll
    for (int ni = 0; ni < 8; ni++) {
        const int d = h4 * 64 + ni * 8 + tg * 2;
        const int r0 = wq + g, r1 = wq + g + 8;
        *(float2*)&g_ctx[(size_t)(b * SEQ + r0) * EMBD + d] =
            make_float2(to_tf32(o[ni][0] * inv0), to_tf32(o[ni][1] * inv0));
        *(float2*)&g_ctx[(size_t)(b * SEQ + r1) * EMBD + d] =
            make_float2(to_tf32(o[ni][2] * inv1), to_tf32(o[ni][3] * inv1));
    }
}

// ---------------------------------------------------------------------------
extern "C" void kernel_launch(void* const* d_in, const int* in_sizes, int n_in,
                              void* d_out, int out_size)
{
    const float* Xk = (const float*)d_in[0];
    const float* Xv = (const float*)d_in[1];
    const float* Xq = (const float*)d_in[2];
    const float* Wk = (const float*)d_in[3];
    const float* Wv = (const float*)d_in[4];
    const float* Wq = (const float*)d_in[5];
    const float* Wo = (const float*)d_in[6];
    const float* bo = (const float*)d_in[7];
    float* out = (float*)d_out;

    cudaFuncSetAttribute(proj_tc, cudaFuncAttributeMaxDynamicSharedMemorySize, GEMM_SMEM);
    cudaFuncSetAttribute(outproj_tc, cudaFuncAttributeMaxDynamicSharedMemorySize, GEMM_SMEM);
    cudaFuncSetAttribute(attn_tc, cudaFuncAttributeMaxDynamicSharedMemorySize, ATTN_SMEM);

    // 0) pre-round inputs + transpose weights to [N,K] K-major (tf32)
    round_inputs<<<dim3(4096, 3), 256>>>(Xk, Xv, Xq);
    transpose_w<<<dim3(NH, 32, 3), 256>>>(Wk, Wv, Wq);
    transpose_wo<<<dim3(32, 32), 256>>>(Wo);
    // 1) QKV projections (cp.async + ldmatrix + mma tf32, 2 CTAs/SM)
    proj_tc<<<dim3(32, 8, 3), 256, GEMM_SMEM>>>();
    // 2) causal flash attention (cp.async double-buffered, ldmatrix frags)
    attn_tc<<<dim3(BH, 8), 256, ATTN_SMEM>>>();
    // 3) output projection + bias + relu (2 CTAs/SM)
    outproj_tc<<<dim3(32, 8), 256, GEMM_SMEM>>>(bo, out);
}